// round 6
// baseline (speedup 1.0000x reference)
#include <cuda_runtime.h>

#define EPSV 1e-5f

// ---------------- scratch (device globals; no allocation allowed) ----------------
#define MAXN 100000
#define MAXG 500
#define MAXDEG 64   // Poisson(10): P(deg>64) ~ 1e-30

__device__ int   g_cnt_i[MAXN];              // in-degree / bin cursor
__device__ int   g_csc[MAXN * MAXDEG];       // fixed-stride CSC: src lists per dst
__device__ float g_hs1[(MAXN + 1) * 64];     // (x@W1)*dis ; row MAXN = zero dummy
__device__ float g_hs2[(MAXN + 1) * 32];     // (y1@W2)*dis ; row MAXN = zero dummy
__device__ float g_sums[MAXG * 32];
__device__ float g_cnt[MAXG];

// ---------------- binning: CSC build + zero pool accumulators (fused) ----------------
__global__ void bin_kernel(const int* __restrict__ ei, int nE) {
    int t = blockIdx.x * blockDim.x + threadIdx.x;
    if (t < MAXG * 32) g_sums[t] = 0.f;
    if (t < MAXG) g_cnt[t] = 0.f;
    if (t >= nE) return;
    int s = ei[t];
    int d = ei[nE + t];
    int p = atomicAdd(&g_cnt_i[d], 1);
    if (p < MAXDEG) g_csc[(size_t)d * MAXDEG + p] = s;
}

// ---------------- pad: make every warp-group's edge loop branch-free ----------------
// Pads each node's CSC list with dummy index MAXN up to ceil16(max degree of its
// 4-node group). Also zeroes the dummy feature rows.
__global__ void pad_kernel(int n) {
    int t = blockIdx.x * blockDim.x + threadIdx.x;
    if (t < 64) g_hs1[(size_t)MAXN * 64 + t] = 0.f;
    if (t < 32) g_hs2[(size_t)MAXN * 32 + t] = 0.f;
    if (t >= n) return;

    int q0 = t & ~3;
    int maxd = 0;
#pragma unroll
    for (int k = 0; k < 4; k++) {
        int u = q0 + k;
        int du = (u < n) ? min(g_cnt_i[u], MAXDEG) : 0;
        maxd = max(maxd, du);
    }
    int dpad = min((maxd + 15) & ~15, MAXDEG);
    int d = min(g_cnt_i[t], MAXDEG);
    int* row = &g_csc[(size_t)t * MAXDEG];
    for (int p = d; p < dpad; p++) row[p] = MAXN;
}

// ---------------- layer-1 GEMM: hs1[row] = (x[row] @ W1) * rsqrt(deg+1) ----------------
__global__ void __launch_bounds__(256) gemm1_kernel(const float* __restrict__ X,
                                                    const float* __restrict__ W, int n) {
    __shared__ float sW[64 * 64];
    int tid = threadIdx.x;
    for (int i = tid * 4; i < 64 * 64; i += 256 * 4)
        *reinterpret_cast<float4*>(&sW[i]) = *reinterpret_cast<const float4*>(&W[i]);
    __syncthreads();

    int warp = tid >> 5, lane = tid & 31;
    int row0 = blockIdx.x * 64 + warp * 8;
    if (row0 >= n) return;

    float acc0[8], acc1[8];
#pragma unroll
    for (int r = 0; r < 8; r++) { acc0[r] = 0.f; acc1[r] = 0.f; }

#pragma unroll
    for (int kc = 0; kc < 64; kc += 4) {
        float w0[4], w1[4];
#pragma unroll
        for (int kk = 0; kk < 4; kk++) {
            w0[kk] = sW[(kc + kk) * 64 + lane];
            w1[kk] = sW[(kc + kk) * 64 + lane + 32];
        }
#pragma unroll
        for (int r = 0; r < 8; r++) {
            int row = min(row0 + r, n - 1);
            float4 xv = *reinterpret_cast<const float4*>(&X[(size_t)row * 64 + kc]);
            acc0[r] += xv.x * w0[0] + xv.y * w0[1] + xv.z * w0[2] + xv.w * w0[3];
            acc1[r] += xv.x * w1[0] + xv.y * w1[1] + xv.z * w1[2] + xv.w * w1[3];
        }
    }

#pragma unroll
    for (int r = 0; r < 8; r++) {
        int row = row0 + r;
        if (row >= n) break;
        float dv = rsqrtf((float)g_cnt_i[row] + 1.0f);
        g_hs1[(size_t)row * 64 + lane] = acc0[r] * dv;
        g_hs1[(size_t)row * 64 + lane + 32] = acc1[r] * dv;
    }
}

// ---------------- fused pull-1 + GEMM-2 (branch-free edge loop) ----------------
__global__ void __launch_bounds__(256) pull1_gemm2_kernel(
    const float* __restrict__ b1, const float* __restrict__ g1,
    const float* __restrict__ be1, const float* __restrict__ m1,
    const float* __restrict__ v1, const float* __restrict__ W2, int n) {
    __shared__ float sW2[64 * 32];   // 8 KB
    __shared__ float sy1[16][64];    // 4 KB, warp-private slots

    int tid = threadIdx.x;
    for (int i = tid * 4; i < 64 * 32; i += 256 * 4)
        *reinterpret_cast<float4*>(&sW2[i]) = *reinterpret_cast<const float4*>(&W2[i]);
    __syncthreads();

    int wp = tid >> 5;
    int lane = tid & 31;
    int wid = blockIdx.x * 8 + wp;
    if (wid * 2 >= n) return;

    // ---- phase 1: pull over hs1, 2 nodes/warp ----
    int half = lane >> 4;
    int li = lane & 15;
    int hbase = half << 4;
    int v = min(wid * 2 + half, n - 1);
    int dt = g_cnt_i[v];
    int d = min(dt, MAXDEG);
    int dmax = max(d, __shfl_xor_sync(0xffffffffu, d, 16));
    int dpad = (dmax + 15) & ~15;    // padded region is valid up to here
    const int* row = &g_csc[(size_t)v * MAXDEG];
    const float* hp = &g_hs1[li * 4];

    float4 aA = make_float4(0.f, 0.f, 0.f, 0.f);
    float4 aB = make_float4(0.f, 0.f, 0.f, 0.f);

    for (int i = 0; i < dpad; i += 16) {
        int sl = row[i + li];
#pragma unroll
        for (int j = 0; j < 16; j += 2) {
            int s0 = __shfl_sync(0xffffffffu, sl, hbase + j);
            int s1 = __shfl_sync(0xffffffffu, sl, hbase + j + 1);
            float4 h0 = *reinterpret_cast<const float4*>(&hp[(size_t)s0 * 64]);
            float4 h1 = *reinterpret_cast<const float4*>(&hp[(size_t)s1 * 64]);
            aA.x += h0.x; aA.y += h0.y; aA.z += h0.z; aA.w += h0.w;
            aB.x += h1.x; aB.y += h1.y; aB.z += h1.z; aB.w += h1.w;
        }
    }

    float dvp = rsqrtf((float)dt + 1.0f);
    float4 hv = *reinterpret_cast<const float4*>(&g_hs1[(size_t)v * 64 + li * 4]);
    float pre[4] = {dvp * (aA.x + aB.x + hv.x), dvp * (aA.y + aB.y + hv.y),
                    dvp * (aA.z + aB.z + hv.z), dvp * (aA.w + aB.w + hv.w)};
    float4 o;
    float* op = &o.x;
#pragma unroll
    for (int c = 0; c < 4; c++) {
        int f = li * 4 + c;
        float s = g1[f] * rsqrtf(v1[f] + EPSV);
        float sh = (b1[f] - m1[f]) * s + be1[f];
        op[c] = fmaxf(pre[c] * s + sh, 0.f);
    }
    int slot = wp * 2 + half;
    *reinterpret_cast<float4*>(&sy1[slot][li * 4]) = o;
    __syncwarp();

    // ---- phase 2: GEMV 64x32 per node, lane = output col ----
    int vA = wid * 2;
    int vB = wid * 2 + 1;
    float accA = 0.f, accB = 0.f;
    const float* yA = sy1[wp * 2];
    const float* yB = sy1[wp * 2 + 1];

#pragma unroll
    for (int kc = 0; kc < 64; kc += 4) {
        float w0 = sW2[(kc + 0) * 32 + lane];
        float w1 = sW2[(kc + 1) * 32 + lane];
        float w2 = sW2[(kc + 2) * 32 + lane];
        float w3 = sW2[(kc + 3) * 32 + lane];
        float4 xA = *reinterpret_cast<const float4*>(&yA[kc]);
        float4 xB = *reinterpret_cast<const float4*>(&yB[kc]);
        accA += xA.x * w0 + xA.y * w1 + xA.z * w2 + xA.w * w3;
        accB += xB.x * w0 + xB.y * w1 + xB.z * w2 + xB.w * w3;
    }

    if (vA < n) {
        float dvA = rsqrtf((float)g_cnt_i[vA] + 1.0f);
        g_hs2[(size_t)vA * 32 + lane] = accA * dvA;
    }
    if (vB < n) {
        float dvB = rsqrtf((float)g_cnt_i[vB] + 1.0f);
        g_hs2[(size_t)vB * 32 + lane] = accB * dvB;
    }
}

// ---------------- fused pull-2 + mean-pool (branch-free edge loop) ----------------
__global__ void __launch_bounds__(256) pull2_pool_kernel(
    const int* __restrict__ batch,
    const float* __restrict__ b2, const float* __restrict__ g2,
    const float* __restrict__ be2, const float* __restrict__ m2,
    const float* __restrict__ v2, int n) {
    int wid = (blockIdx.x * blockDim.x + threadIdx.x) >> 5;
    if (wid * 4 >= n) return;
    int lane = threadIdx.x & 31;
    int q = lane >> 3;
    int li = lane & 7;
    int qbase = q << 3;

    int vraw = wid * 4 + q;
    int v = min(vraw, n - 1);
    int dt = g_cnt_i[v];
    int d = min(dt, MAXDEG);
    int dp = max(d, __shfl_xor_sync(0xffffffffu, d, 8));
    int dmax = max(dp, __shfl_xor_sync(0xffffffffu, dp, 16));
    int dpad = (dmax + 7) & ~7;   // padded to ceil16 of quad max >= this
    const int* row = &g_csc[(size_t)v * MAXDEG];
    const float* hp = &g_hs2[li * 4];

    float4 aA = make_float4(0.f, 0.f, 0.f, 0.f);
    float4 aB = make_float4(0.f, 0.f, 0.f, 0.f);

    for (int i = 0; i < dpad; i += 8) {
        int sl = row[i + li];
#pragma unroll
        for (int j = 0; j < 8; j += 2) {
            int s0 = __shfl_sync(0xffffffffu, sl, qbase + j);
            int s1 = __shfl_sync(0xffffffffu, sl, qbase + j + 1);
            float4 h0 = *reinterpret_cast<const float4*>(&hp[(size_t)s0 * 32]);
            float4 h1 = *reinterpret_cast<const float4*>(&hp[(size_t)s1 * 32]);
            aA.x += h0.x; aA.y += h0.y; aA.z += h0.z; aA.w += h0.w;
            aB.x += h1.x; aB.y += h1.y; aB.z += h1.z; aB.w += h1.w;
        }
    }

    if (vraw >= n) return;

    float dv = rsqrtf((float)dt + 1.0f);
    float4 hv = *reinterpret_cast<const float4*>(&g_hs2[(size_t)v * 32 + li * 4]);
    float pre[4] = {dv * (aA.x + aB.x + hv.x), dv * (aA.y + aB.y + hv.y),
                    dv * (aA.z + aB.z + hv.z), dv * (aA.w + aB.w + hv.w)};
    float o[4];
#pragma unroll
    for (int c = 0; c < 4; c++) {
        int f = li * 4 + c;
        float s = g2[f] * rsqrtf(v2[f] + EPSV);
        float sh = (b2[f] - m2[f]) * s + be2[f];
        o[c] = fmaxf(pre[c] * s + sh, 0.f);
    }

    int g = batch[v];
    float* a = &g_sums[g * 32 + li * 4];
    asm volatile("red.global.add.v4.f32 [%0], {%1,%2,%3,%4};"
                 :: "l"(a), "f"(o[0]), "f"(o[1]), "f"(o[2]), "f"(o[3])
                 : "memory");
    if (li == 0) atomicAdd(&g_cnt[g], 1.0f);
}

// ---------------- classifier ----------------
__global__ void classifier_kernel(const float* __restrict__ Wc1, const float* __restrict__ bc1,
                                  const float* __restrict__ Wc2, const float* __restrict__ bc2,
                                  float* __restrict__ out, int ngraphs) {
    __shared__ float sW1[32 * 16], sb1[16], sW2[16 * 2], sb2[2];
    int tid = threadIdx.x;
    if (tid < 512) sW1[tid] = Wc1[tid];
    if (tid < 16) sb1[tid] = bc1[tid];
    if (tid < 32) sW2[tid] = Wc2[tid];
    if (tid < 2) sb2[tid] = bc2[tid];
    __syncthreads();

    int g = tid;
    if (g >= ngraphs) return;
    float inv = 1.0f / fmaxf(g_cnt[g], 1.0f);
    float z[32];
#pragma unroll
    for (int f = 0; f < 32; f++) z[f] = g_sums[g * 32 + f] * inv;
    float o0 = sb2[0], o1 = sb2[1];
#pragma unroll
    for (int j = 0; j < 16; j++) {
        float h = sb1[j];
#pragma unroll
        for (int f = 0; f < 32; f++) h += z[f] * sW1[f * 16 + j];
        h = fmaxf(h, 0.f);
        o0 += h * sW2[j * 2 + 0];
        o1 += h * sW2[j * 2 + 1];
    }
    out[g * 2 + 0] = o0;
    out[g * 2 + 1] = o1;
}

// ---------------- launch ----------------
extern "C" void kernel_launch(void* const* d_in, const int* in_sizes, int n_in,
                              void* d_out, int out_size) {
    const float* x   = (const float*)d_in[0];
    const int*   ei  = (const int*)d_in[1];
    const int*   bat = (const int*)d_in[2];
    const float* W1  = (const float*)d_in[3];
    const float* b1  = (const float*)d_in[4];
    const float* g1  = (const float*)d_in[5];
    const float* be1 = (const float*)d_in[6];
    const float* m1  = (const float*)d_in[7];
    const float* v1  = (const float*)d_in[8];
    const float* W2  = (const float*)d_in[9];
    const float* b2  = (const float*)d_in[10];
    const float* g2  = (const float*)d_in[11];
    const float* be2 = (const float*)d_in[12];
    const float* m2  = (const float*)d_in[13];
    const float* v2  = (const float*)d_in[14];
    const float* Wc1 = (const float*)d_in[15];
    const float* bc1 = (const float*)d_in[16];
    const float* Wc2 = (const float*)d_in[17];
    const float* bc2 = (const float*)d_in[18];

    int n  = in_sizes[0] / 64;   // nodes
    int nE = in_sizes[1] / 2;    // edges
    int ngraphs = out_size / 2;

    void* p_cnti;
    cudaGetSymbolAddress(&p_cnti, g_cnt_i);
    cudaMemsetAsync(p_cnti, 0, (size_t)n * sizeof(int));

    bin_kernel<<<(nE + 255) / 256, 256>>>(ei, nE);
    pad_kernel<<<(n + 255) / 256, 256>>>(n);

    gemm1_kernel<<<(n + 63) / 64, 256>>>(x, W1, n);
    pull1_gemm2_kernel<<<(n + 15) / 16, 256>>>(b1, g1, be1, m1, v1, W2, n);
    {
        int warps = (n + 3) / 4;
        pull2_pool_kernel<<<(warps * 32 + 255) / 256, 256>>>(bat, b2, g2, be2, m2, v2, n);
    }
    classifier_kernel<<<1, 512>>>(Wc1, bc1, Wc2, bc2, (float*)d_out, ngraphs);
}

// round 7
// speedup vs baseline: 1.0730x; 1.0730x over previous
#include <cuda_runtime.h>
#include <cuda_fp16.h>

#define EPSV 1e-5f

// ---------------- scratch (device globals; no allocation allowed) ----------------
#define MAXN 100000
#define MAXG 500
#define MAXDEG 64   // Poisson(10): P(deg>64) ~ 1e-30

__device__ int    g_cnt_i[MAXN];              // in-degree / bin cursor
__device__ int    g_csc[MAXN * MAXDEG];       // fixed-stride CSC: src lists per dst
__device__ __half g_hs1h[(MAXN + 1) * 64];    // (x@W1)*dis, fp16 ; row MAXN = zeros
__device__ __half g_hs2h[(MAXN + 1) * 32];    // (y1@W2)*dis, fp16 ; row MAXN = zeros
__device__ float  g_sums[MAXG * 32];
__device__ float  g_cnt[MAXG];

// ---------------- binning: CSC build + zero pool accumulators (fused) ----------------
__global__ void bin_kernel(const int* __restrict__ ei, int nE) {
    int t = blockIdx.x * blockDim.x + threadIdx.x;
    if (t < MAXG * 32) g_sums[t] = 0.f;
    if (t < MAXG) g_cnt[t] = 0.f;
    if (t >= nE) return;
    int s = ei[t];
    int d = ei[nE + t];
    int p = atomicAdd(&g_cnt_i[d], 1);
    if (p < MAXDEG) g_csc[(size_t)d * MAXDEG + p] = s;
}

// ---------------- pad: dummy-fill CSC rows + zero dummy feature rows ----------------
// Pads each node's list with index MAXN up to ceil16(max degree of its 4-node group)
// (covers pull2's branch-free windows). Dummy rows are zero, so padded edges add 0.
__global__ void pad_kernel(int n) {
    int t = blockIdx.x * blockDim.x + threadIdx.x;
    if (t < 64) g_hs1h[(size_t)MAXN * 64 + t] = __float2half(0.f);
    if (t < 32) g_hs2h[(size_t)MAXN * 32 + t] = __float2half(0.f);
    if (t >= n) return;

    int q0 = t & ~3;
    int maxd = 0;
#pragma unroll
    for (int k = 0; k < 4; k++) {
        int u = q0 + k;
        int du = (u < n) ? min(g_cnt_i[u], MAXDEG) : 0;
        maxd = max(maxd, du);
    }
    int dpad = min((maxd + 15) & ~15, MAXDEG);
    int d = min(g_cnt_i[t], MAXDEG);
    int* row = &g_csc[(size_t)t * MAXDEG];
    for (int p = d; p < dpad; p++) row[p] = MAXN;
}

// ---------------- layer-1 GEMM: hs1[row] = (x[row] @ W1) * rsqrt(deg+1), fp16 out ----
// Lane owns adjacent cols {2*lane, 2*lane+1} so the store packs into one half2.
__global__ void __launch_bounds__(256) gemm1_kernel(const float* __restrict__ X,
                                                    const float* __restrict__ W, int n) {
    __shared__ float sW[64 * 64];
    int tid = threadIdx.x;
    for (int i = tid * 4; i < 64 * 64; i += 256 * 4)
        *reinterpret_cast<float4*>(&sW[i]) = *reinterpret_cast<const float4*>(&W[i]);
    __syncthreads();

    int warp = tid >> 5, lane = tid & 31;
    int row0 = blockIdx.x * 64 + warp * 8;
    if (row0 >= n) return;

    float acc0[8], acc1[8];
#pragma unroll
    for (int r = 0; r < 8; r++) { acc0[r] = 0.f; acc1[r] = 0.f; }

#pragma unroll
    for (int kc = 0; kc < 64; kc += 4) {
        float2 w[4];
#pragma unroll
        for (int kk = 0; kk < 4; kk++)
            w[kk] = *reinterpret_cast<const float2*>(&sW[(kc + kk) * 64 + lane * 2]);
#pragma unroll
        for (int r = 0; r < 8; r++) {
            int row = min(row0 + r, n - 1);
            float4 xv = *reinterpret_cast<const float4*>(&X[(size_t)row * 64 + kc]);
            acc0[r] += xv.x * w[0].x + xv.y * w[1].x + xv.z * w[2].x + xv.w * w[3].x;
            acc1[r] += xv.x * w[0].y + xv.y * w[1].y + xv.z * w[2].y + xv.w * w[3].y;
        }
    }

#pragma unroll
    for (int r = 0; r < 8; r++) {
        int row = row0 + r;
        if (row >= n) break;
        float dv = rsqrtf((float)g_cnt_i[row] + 1.0f);
        __half2 h = __floats2half2_rn(acc0[r] * dv, acc1[r] * dv);
        *reinterpret_cast<__half2*>(&g_hs1h[(size_t)row * 64 + lane * 2]) = h;
    }
}

// fp16 gather helper: load 4 halves (8B) as 4 floats
__device__ __forceinline__ float4 ld_h4(const __half* p) {
    uint2 u = *reinterpret_cast<const uint2*>(p);
    float2 a = __half22float2(*reinterpret_cast<const __half2*>(&u.x));
    float2 b = __half22float2(*reinterpret_cast<const __half2*>(&u.y));
    return make_float4(a.x, a.y, b.x, b.y);
}

// ---------------- fused pull-1 + GEMM-2 ----------------
// Phase 1 (2 nodes/warp, half-warp each, lane=4 cols): exact edge count, dummy-index
// guard, 4-wide unconditional body. Phase 2: hs2[v] = (y1@W2)*dis, fp16 out.
__global__ void __launch_bounds__(256) pull1_gemm2_kernel(
    const float* __restrict__ b1, const float* __restrict__ g1,
    const float* __restrict__ be1, const float* __restrict__ m1,
    const float* __restrict__ v1, const float* __restrict__ W2, int n) {
    __shared__ float sW2[64 * 32];   // 8 KB
    __shared__ float sy1[16][64];    // 4 KB, warp-private slots

    int tid = threadIdx.x;
    for (int i = tid * 4; i < 64 * 32; i += 256 * 4)
        *reinterpret_cast<float4*>(&sW2[i]) = *reinterpret_cast<const float4*>(&W2[i]);
    __syncthreads();

    int wp = tid >> 5;
    int lane = tid & 31;
    int wid = blockIdx.x * 8 + wp;
    if (wid * 2 >= n) return;

    // ---- phase 1 ----
    int half = lane >> 4;
    int li = lane & 15;
    int hbase = half << 4;
    int v = min(wid * 2 + half, n - 1);
    int dt = g_cnt_i[v];
    int d = min(dt, MAXDEG);
    int dmax = max(d, __shfl_xor_sync(0xffffffffu, d, 16));
    const int* row = &g_csc[(size_t)v * MAXDEG];
    const __half* hp = &g_hs1h[li * 4];

    float4 aA = make_float4(0.f, 0.f, 0.f, 0.f);
    float4 aB = make_float4(0.f, 0.f, 0.f, 0.f);

    for (int i = 0; i < dmax; i += 16) {
        int sl = (i + li < d) ? row[i + li] : MAXN;   // dummy -> zero row
        int m = min(16, dmax - i);
        int j = 0;
        for (; j + 3 < m; j += 4) {
            int s0 = __shfl_sync(0xffffffffu, sl, hbase + j);
            int s1 = __shfl_sync(0xffffffffu, sl, hbase + j + 1);
            int s2 = __shfl_sync(0xffffffffu, sl, hbase + j + 2);
            int s3 = __shfl_sync(0xffffffffu, sl, hbase + j + 3);
            float4 h0 = ld_h4(&hp[(size_t)s0 * 64]);
            float4 h1 = ld_h4(&hp[(size_t)s1 * 64]);
            float4 h2 = ld_h4(&hp[(size_t)s2 * 64]);
            float4 h3 = ld_h4(&hp[(size_t)s3 * 64]);
            aA.x += h0.x; aA.y += h0.y; aA.z += h0.z; aA.w += h0.w;
            aB.x += h1.x; aB.y += h1.y; aB.z += h1.z; aB.w += h1.w;
            aA.x += h2.x; aA.y += h2.y; aA.z += h2.z; aA.w += h2.w;
            aB.x += h3.x; aB.y += h3.y; aB.z += h3.z; aB.w += h3.w;
        }
        for (; j < m; j++) {
            int s0 = __shfl_sync(0xffffffffu, sl, hbase + j);
            float4 h0 = ld_h4(&hp[(size_t)s0 * 64]);
            aA.x += h0.x; aA.y += h0.y; aA.z += h0.z; aA.w += h0.w;
        }
    }

    float dvp = rsqrtf((float)dt + 1.0f);
    float4 hv = ld_h4(&g_hs1h[(size_t)v * 64 + li * 4]);
    float pre[4] = {dvp * (aA.x + aB.x + hv.x), dvp * (aA.y + aB.y + hv.y),
                    dvp * (aA.z + aB.z + hv.z), dvp * (aA.w + aB.w + hv.w)};
    float4 o;
    float* op = &o.x;
#pragma unroll
    for (int c = 0; c < 4; c++) {
        int f = li * 4 + c;
        float s = g1[f] * rsqrtf(v1[f] + EPSV);
        float sh = (b1[f] - m1[f]) * s + be1[f];
        op[c] = fmaxf(pre[c] * s + sh, 0.f);
    }
    int slot = wp * 2 + half;
    *reinterpret_cast<float4*>(&sy1[slot][li * 4]) = o;
    __syncwarp();

    // ---- phase 2: GEMV 64x32 per node, lane = output col ----
    int vA = wid * 2;
    int vB = wid * 2 + 1;
    float accA = 0.f, accB = 0.f;
    const float* yA = sy1[wp * 2];
    const float* yB = sy1[wp * 2 + 1];

#pragma unroll
    for (int kc = 0; kc < 64; kc += 4) {
        float w0 = sW2[(kc + 0) * 32 + lane];
        float w1 = sW2[(kc + 1) * 32 + lane];
        float w2 = sW2[(kc + 2) * 32 + lane];
        float w3 = sW2[(kc + 3) * 32 + lane];
        float4 xA = *reinterpret_cast<const float4*>(&yA[kc]);
        float4 xB = *reinterpret_cast<const float4*>(&yB[kc]);
        accA += xA.x * w0 + xA.y * w1 + xA.z * w2 + xA.w * w3;
        accB += xB.x * w0 + xB.y * w1 + xB.z * w2 + xB.w * w3;
    }

    if (vA < n) {
        float dvA = rsqrtf((float)g_cnt_i[vA] + 1.0f);
        g_hs2h[(size_t)vA * 32 + lane] = __float2half_rn(accA * dvA);
    }
    if (vB < n) {
        float dvB = rsqrtf((float)g_cnt_i[vB] + 1.0f);
        g_hs2h[(size_t)vB * 32 + lane] = __float2half_rn(accB * dvB);
    }
}

// ---------------- fused pull-2 + mean-pool (branch-free padded loop, fp16) ----------
__global__ void __launch_bounds__(256) pull2_pool_kernel(
    const int* __restrict__ batch,
    const float* __restrict__ b2, const float* __restrict__ g2,
    const float* __restrict__ be2, const float* __restrict__ m2,
    const float* __restrict__ v2, int n) {
    int wid = (blockIdx.x * blockDim.x + threadIdx.x) >> 5;
    if (wid * 4 >= n) return;
    int lane = threadIdx.x & 31;
    int q = lane >> 3;
    int li = lane & 7;
    int qbase = q << 3;

    int vraw = wid * 4 + q;
    int v = min(vraw, n - 1);
    int dt = g_cnt_i[v];
    int d = min(dt, MAXDEG);
    int dp = max(d, __shfl_xor_sync(0xffffffffu, d, 8));
    int dmax = max(dp, __shfl_xor_sync(0xffffffffu, dp, 16));
    int dpad = (dmax + 7) & ~7;   // padded region valid to ceil16 of quad max
    const int* row = &g_csc[(size_t)v * MAXDEG];
    const __half* hp = &g_hs2h[li * 4];

    float4 aA = make_float4(0.f, 0.f, 0.f, 0.f);
    float4 aB = make_float4(0.f, 0.f, 0.f, 0.f);

    for (int i = 0; i < dpad; i += 8) {
        int sl = row[i + li];
#pragma unroll
        for (int j = 0; j < 8; j += 2) {
            int s0 = __shfl_sync(0xffffffffu, sl, qbase + j);
            int s1 = __shfl_sync(0xffffffffu, sl, qbase + j + 1);
            float4 h0 = ld_h4(&hp[(size_t)s0 * 32]);
            float4 h1 = ld_h4(&hp[(size_t)s1 * 32]);
            aA.x += h0.x; aA.y += h0.y; aA.z += h0.z; aA.w += h0.w;
            aB.x += h1.x; aB.y += h1.y; aB.z += h1.z; aB.w += h1.w;
        }
    }

    if (vraw >= n) return;

    float dv = rsqrtf((float)dt + 1.0f);
    float4 hv = ld_h4(&g_hs2h[(size_t)v * 32 + li * 4]);
    float pre[4] = {dv * (aA.x + aB.x + hv.x), dv * (aA.y + aB.y + hv.y),
                    dv * (aA.z + aB.z + hv.z), dv * (aA.w + aB.w + hv.w)};
    float o[4];
#pragma unroll
    for (int c = 0; c < 4; c++) {
        int f = li * 4 + c;
        float s = g2[f] * rsqrtf(v2[f] + EPSV);
        float sh = (b2[f] - m2[f]) * s + be2[f];
        o[c] = fmaxf(pre[c] * s + sh, 0.f);
    }

    int g = batch[v];
    float* a = &g_sums[g * 32 + li * 4];
    asm volatile("red.global.add.v4.f32 [%0], {%1,%2,%3,%4};"
                 :: "l"(a), "f"(o[0]), "f"(o[1]), "f"(o[2]), "f"(o[3])
                 : "memory");
    if (li == 0) atomicAdd(&g_cnt[g], 1.0f);
}

// ---------------- classifier ----------------
__global__ void classifier_kernel(const float* __restrict__ Wc1, const float* __restrict__ bc1,
                                  const float* __restrict__ Wc2, const float* __restrict__ bc2,
                                  float* __restrict__ out, int ngraphs) {
    __shared__ float sW1[32 * 16], sb1[16], sW2[16 * 2], sb2[2];
    int tid = threadIdx.x;
    if (tid < 512) sW1[tid] = Wc1[tid];
    if (tid < 16) sb1[tid] = bc1[tid];
    if (tid < 32) sW2[tid] = Wc2[tid];
    if (tid < 2) sb2[tid] = bc2[tid];
    __syncthreads();

    int g = tid;
    if (g >= ngraphs) return;
    float inv = 1.0f / fmaxf(g_cnt[g], 1.0f);
    float z[32];
#pragma unroll
    for (int f = 0; f < 32; f++) z[f] = g_sums[g * 32 + f] * inv;
    float o0 = sb2[0], o1 = sb2[1];
#pragma unroll
    for (int j = 0; j < 16; j++) {
        float h = sb1[j];
#pragma unroll
        for (int f = 0; f < 32; f++) h += z[f] * sW1[f * 16 + j];
        h = fmaxf(h, 0.f);
        o0 += h * sW2[j * 2 + 0];
        o1 += h * sW2[j * 2 + 1];
    }
    out[g * 2 + 0] = o0;
    out[g * 2 + 1] = o1;
}

// ---------------- launch ----------------
extern "C" void kernel_launch(void* const* d_in, const int* in_sizes, int n_in,
                              void* d_out, int out_size) {
    const float* x   = (const float*)d_in[0];
    const int*   ei  = (const int*)d_in[1];
    const int*   bat = (const int*)d_in[2];
    const float* W1  = (const float*)d_in[3];
    const float* b1  = (const float*)d_in[4];
    const float* g1  = (const float*)d_in[5];
    const float* be1 = (const float*)d_in[6];
    const float* m1  = (const float*)d_in[7];
    const float* v1  = (const float*)d_in[8];
    const float* W2  = (const float*)d_in[9];
    const float* b2  = (const float*)d_in[10];
    const float* g2  = (const float*)d_in[11];
    const float* be2 = (const float*)d_in[12];
    const float* m2  = (const float*)d_in[13];
    const float* v2  = (const float*)d_in[14];
    const float* Wc1 = (const float*)d_in[15];
    const float* bc1 = (const float*)d_in[16];
    const float* Wc2 = (const float*)d_in[17];
    const float* bc2 = (const float*)d_in[18];

    int n  = in_sizes[0] / 64;   // nodes
    int nE = in_sizes[1] / 2;    // edges
    int ngraphs = out_size / 2;

    void* p_cnti;
    cudaGetSymbolAddress(&p_cnti, g_cnt_i);
    cudaMemsetAsync(p_cnti, 0, (size_t)n * sizeof(int));

    bin_kernel<<<(nE + 255) / 256, 256>>>(ei, nE);
    pad_kernel<<<(n + 255) / 256, 256>>>(n);

    gemm1_kernel<<<(n + 63) / 64, 256>>>(x, W1, n);
    pull1_gemm2_kernel<<<(n + 15) / 16, 256>>>(b1, g1, be1, m1, v1, W2, n);
    {
        int warps = (n + 3) / 4;
        pull2_pool_kernel<<<(warps * 32 + 255) / 256, 256>>>(bat, b2, g2, be2, m2, v2, n);
    }
    classifier_kernel<<<1, 512>>>(Wc1, bc1, Wc2, bc2, (float*)d_out, ngraphs);
}

// round 8
// speedup vs baseline: 1.1418x; 1.0641x over previous
#include <cuda_runtime.h>
#include <cuda_fp16.h>

#define EPSV 1e-5f

// ---------------- scratch (device globals; no allocation allowed) ----------------
#define MAXN 100000
#define MAXG 500
#define MAXDEG 64   // Poisson(10): P(deg>64) ~ 1e-30

__device__ int    g_cnt_i[MAXN];              // in-degree / bin cursor
__device__ int    g_csc[MAXN * MAXDEG];       // fixed-stride CSC: src lists per dst
__device__ __half g_hs1h[(MAXN + 1) * 64];    // (x@W1)*dis, fp16 ; row MAXN = zeros
__device__ __half g_hs2h[(MAXN + 1) * 32];    // (y1@W2)*dis, fp16 ; row MAXN = zeros
__device__ float  g_sums[MAXG * 32];
__device__ float  g_cnt[MAXG];

// ---------------- binning: CSC build + zero pool accumulators (fused) ----------------
__global__ void bin_kernel(const int* __restrict__ ei, int nE) {
    int t = blockIdx.x * blockDim.x + threadIdx.x;
    if (t < MAXG * 32) g_sums[t] = 0.f;
    if (t < MAXG) g_cnt[t] = 0.f;
    if (t >= nE) return;
    int s = ei[t];
    int d = ei[nE + t];
    int p = atomicAdd(&g_cnt_i[d], 1);
    if (p < MAXDEG) g_csc[(size_t)d * MAXDEG + p] = s;
}

// ---------------- pad: dummy-fill CSC rows to ceil4 of 4-node-group max ----------------
// Dummy index MAXN points at an all-zero feature row, so padded edges add 0.
// pull1 reads up to ceil4(pair max) and pull2 up to ceil4(quad max); quad >= pair.
__global__ void pad_kernel(int n) {
    int t = blockIdx.x * blockDim.x + threadIdx.x;
    if (t < 64) g_hs1h[(size_t)MAXN * 64 + t] = __float2half(0.f);
    if (t < 32) g_hs2h[(size_t)MAXN * 32 + t] = __float2half(0.f);
    if (t >= n) return;

    int q0 = t & ~3;
    int maxd = 0;
#pragma unroll
    for (int k = 0; k < 4; k++) {
        int u = q0 + k;
        int du = (u < n) ? min(g_cnt_i[u], MAXDEG) : 0;
        maxd = max(maxd, du);
    }
    int dpad = min((maxd + 3) & ~3, MAXDEG);
    int d = min(g_cnt_i[t], MAXDEG);
    int* row = &g_csc[(size_t)t * MAXDEG];
    for (int p = d; p < dpad; p++) row[p] = MAXN;
}

// ---------------- layer-1 GEMM: hs1[row] = (x[row] @ W1) * rsqrt(deg+1), fp16 out ----
__global__ void __launch_bounds__(256) gemm1_kernel(const float* __restrict__ X,
                                                    const float* __restrict__ W, int n) {
    __shared__ float sW[64 * 64];
    int tid = threadIdx.x;
    for (int i = tid * 4; i < 64 * 64; i += 256 * 4)
        *reinterpret_cast<float4*>(&sW[i]) = *reinterpret_cast<const float4*>(&W[i]);
    __syncthreads();

    int warp = tid >> 5, lane = tid & 31;
    int row0 = blockIdx.x * 64 + warp * 8;
    if (row0 >= n) return;

    float acc0[8], acc1[8];
#pragma unroll
    for (int r = 0; r < 8; r++) { acc0[r] = 0.f; acc1[r] = 0.f; }

#pragma unroll
    for (int kc = 0; kc < 64; kc += 4) {
        float2 w[4];
#pragma unroll
        for (int kk = 0; kk < 4; kk++)
            w[kk] = *reinterpret_cast<const float2*>(&sW[(kc + kk) * 64 + lane * 2]);
#pragma unroll
        for (int r = 0; r < 8; r++) {
            int row = min(row0 + r, n - 1);
            float4 xv = *reinterpret_cast<const float4*>(&X[(size_t)row * 64 + kc]);
            acc0[r] += xv.x * w[0].x + xv.y * w[1].x + xv.z * w[2].x + xv.w * w[3].x;
            acc1[r] += xv.x * w[0].y + xv.y * w[1].y + xv.z * w[2].y + xv.w * w[3].y;
        }
    }

#pragma unroll
    for (int r = 0; r < 8; r++) {
        int row = row0 + r;
        if (row >= n) break;
        float dv = rsqrtf((float)g_cnt_i[row] + 1.0f);
        __half2 h = __floats2half2_rn(acc0[r] * dv, acc1[r] * dv);
        *reinterpret_cast<__half2*>(&g_hs1h[(size_t)row * 64 + lane * 2]) = h;
    }
}

// fp16 gather helper: load 4 halves (8B) as 4 floats
__device__ __forceinline__ float4 ld_h4(const __half* p) {
    uint2 u = *reinterpret_cast<const uint2*>(p);
    float2 a = __half22float2(*reinterpret_cast<const __half2*>(&u.x));
    float2 b = __half22float2(*reinterpret_cast<const __half2*>(&u.y));
    return make_float4(a.x, a.y, b.x, b.y);
}

// ---------------- fused pull-1 + GEMM-2 ----------------
// Phase 1: 2 nodes/warp, half-warp per node, lane owns 4 cols. Source indices come
// from uniform int4 loads of the padded CSC row — no shfl, no guards, static body.
// Phase 2: hs2[v] = (y1[v] @ W2) * dis[v], fp16 out.
__global__ void __launch_bounds__(256) pull1_gemm2_kernel(
    const float* __restrict__ b1, const float* __restrict__ g1,
    const float* __restrict__ be1, const float* __restrict__ m1,
    const float* __restrict__ v1, const float* __restrict__ W2, int n) {
    __shared__ float sW2[64 * 32];   // 8 KB
    __shared__ float sy1[16][64];    // 4 KB, warp-private slots

    int tid = threadIdx.x;
    for (int i = tid * 4; i < 64 * 32; i += 256 * 4)
        *reinterpret_cast<float4*>(&sW2[i]) = *reinterpret_cast<const float4*>(&W2[i]);
    __syncthreads();

    int wp = tid >> 5;
    int lane = tid & 31;
    int wid = blockIdx.x * 8 + wp;
    if (wid * 2 >= n) return;

    // ---- phase 1 ----
    int half = lane >> 4;
    int li = lane & 15;
    int v = min(wid * 2 + half, n - 1);
    int dt = g_cnt_i[v];
    int d = min(dt, MAXDEG);
    int dmax = max(d, __shfl_xor_sync(0xffffffffu, d, 16));
    int d4 = (dmax + 3) & ~3;          // padded region valid to ceil4(quad max) >= this
    const int* row = &g_csc[(size_t)v * MAXDEG];
    const __half* hp = &g_hs1h[li * 4];

    float4 aA = make_float4(0.f, 0.f, 0.f, 0.f);
    float4 aB = make_float4(0.f, 0.f, 0.f, 0.f);

    for (int i = 0; i < d4; i += 4) {
        int4 s = *reinterpret_cast<const int4*>(row + i);   // uniform in half-warp
        float4 h0 = ld_h4(&hp[(size_t)s.x * 64]);
        float4 h1 = ld_h4(&hp[(size_t)s.y * 64]);
        float4 h2 = ld_h4(&hp[(size_t)s.z * 64]);
        float4 h3 = ld_h4(&hp[(size_t)s.w * 64]);
        aA.x += h0.x; aA.y += h0.y; aA.z += h0.z; aA.w += h0.w;
        aB.x += h1.x; aB.y += h1.y; aB.z += h1.z; aB.w += h1.w;
        aA.x += h2.x; aA.y += h2.y; aA.z += h2.z; aA.w += h2.w;
        aB.x += h3.x; aB.y += h3.y; aB.z += h3.z; aB.w += h3.w;
    }

    float dvp = rsqrtf((float)dt + 1.0f);
    float4 hv = ld_h4(&g_hs1h[(size_t)v * 64 + li * 4]);
    float pre[4] = {dvp * (aA.x + aB.x + hv.x), dvp * (aA.y + aB.y + hv.y),
                    dvp * (aA.z + aB.z + hv.z), dvp * (aA.w + aB.w + hv.w)};
    float4 o;
    float* op = &o.x;
#pragma unroll
    for (int c = 0; c < 4; c++) {
        int f = li * 4 + c;
        float s = g1[f] * rsqrtf(v1[f] + EPSV);
        float sh = (b1[f] - m1[f]) * s + be1[f];
        op[c] = fmaxf(pre[c] * s + sh, 0.f);
    }
    int slot = wp * 2 + half;
    *reinterpret_cast<float4*>(&sy1[slot][li * 4]) = o;
    __syncwarp();

    // ---- phase 2: GEMV 64x32 per node, lane = output col ----
    int vA = wid * 2;
    int vB = wid * 2 + 1;
    float accA = 0.f, accB = 0.f;
    const float* yA = sy1[wp * 2];
    const float* yB = sy1[wp * 2 + 1];

#pragma unroll
    for (int kc = 0; kc < 64; kc += 4) {
        float w0 = sW2[(kc + 0) * 32 + lane];
        float w1 = sW2[(kc + 1) * 32 + lane];
        float w2 = sW2[(kc + 2) * 32 + lane];
        float w3 = sW2[(kc + 3) * 32 + lane];
        float4 xA = *reinterpret_cast<const float4*>(&yA[kc]);
        float4 xB = *reinterpret_cast<const float4*>(&yB[kc]);
        accA += xA.x * w0 + xA.y * w1 + xA.z * w2 + xA.w * w3;
        accB += xB.x * w0 + xB.y * w1 + xB.z * w2 + xB.w * w3;
    }

    if (vA < n) {
        float dvA = rsqrtf((float)g_cnt_i[vA] + 1.0f);
        g_hs2h[(size_t)vA * 32 + lane] = __float2half_rn(accA * dvA);
    }
    if (vB < n) {
        float dvB = rsqrtf((float)g_cnt_i[vB] + 1.0f);
        g_hs2h[(size_t)vB * 32 + lane] = __float2half_rn(accB * dvB);
    }
}

// ---------------- fused pull-2 + mean-pool ----------------
// 4 nodes/warp, 8 lanes per node, lane owns 4 cols. Uniform int4 index loads, static
// body, padded to ceil4(quad max). Result goes straight to g_sums via vector RED.
__global__ void __launch_bounds__(256) pull2_pool_kernel(
    const int* __restrict__ batch,
    const float* __restrict__ b2, const float* __restrict__ g2,
    const float* __restrict__ be2, const float* __restrict__ m2,
    const float* __restrict__ v2, int n) {
    int wid = (blockIdx.x * blockDim.x + threadIdx.x) >> 5;
    if (wid * 4 >= n) return;
    int lane = threadIdx.x & 31;
    int q = lane >> 3;
    int li = lane & 7;

    int vraw = wid * 4 + q;
    int v = min(vraw, n - 1);
    int dt = g_cnt_i[v];
    int d = min(dt, MAXDEG);
    int dp = max(d, __shfl_xor_sync(0xffffffffu, d, 8));
    int dmax = max(dp, __shfl_xor_sync(0xffffffffu, dp, 16));
    int d4 = (dmax + 3) & ~3;          // == padded length of this quad
    const int* row = &g_csc[(size_t)v * MAXDEG];
    const __half* hp = &g_hs2h[li * 4];

    float4 aA = make_float4(0.f, 0.f, 0.f, 0.f);
    float4 aB = make_float4(0.f, 0.f, 0.f, 0.f);

    for (int i = 0; i < d4; i += 4) {
        int4 s = *reinterpret_cast<const int4*>(row + i);   // uniform in quarter-warp
        float4 h0 = ld_h4(&hp[(size_t)s.x * 32]);
        float4 h1 = ld_h4(&hp[(size_t)s.y * 32]);
        float4 h2 = ld_h4(&hp[(size_t)s.z * 32]);
        float4 h3 = ld_h4(&hp[(size_t)s.w * 32]);
        aA.x += h0.x; aA.y += h0.y; aA.z += h0.z; aA.w += h0.w;
        aB.x += h1.x; aB.y += h1.y; aB.z += h1.z; aB.w += h1.w;
        aA.x += h2.x; aA.y += h2.y; aA.z += h2.z; aA.w += h2.w;
        aB.x += h3.x; aB.y += h3.y; aB.z += h3.z; aB.w += h3.w;
    }

    if (vraw >= n) return;

    float dv = rsqrtf((float)dt + 1.0f);
    float4 hv = ld_h4(&g_hs2h[(size_t)v * 32 + li * 4]);
    float pre[4] = {dv * (aA.x + aB.x + hv.x), dv * (aA.y + aB.y + hv.y),
                    dv * (aA.z + aB.z + hv.z), dv * (aA.w + aB.w + hv.w)};
    float o[4];
#pragma unroll
    for (int c = 0; c < 4; c++) {
        int f = li * 4 + c;
        float s = g2[f] * rsqrtf(v2[f] + EPSV);
        float sh = (b2[f] - m2[f]) * s + be2[f];
        o[c] = fmaxf(pre[c] * s + sh, 0.f);
    }

    int g = batch[v];
    float* a = &g_sums[g * 32 + li * 4];
    asm volatile("red.global.add.v4.f32 [%0], {%1,%2,%3,%4};"
                 :: "l"(a), "f"(o[0]), "f"(o[1]), "f"(o[2]), "f"(o[3])
                 : "memory");
    if (li == 0) atomicAdd(&g_cnt[g], 1.0f);
}

// ---------------- classifier ----------------
__global__ void classifier_kernel(const float* __restrict__ Wc1, const float* __restrict__ bc1,
                                  const float* __restrict__ Wc2, const float* __restrict__ bc2,
                                  float* __restrict__ out, int ngraphs) {
    __shared__ float sW1[32 * 16], sb1[16], sW2[16 * 2], sb2[2];
    int tid = threadIdx.x;
    if (tid < 512) sW1[tid] = Wc1[tid];
    if (tid < 16) sb1[tid] = bc1[tid];
    if (tid < 32) sW2[tid] = Wc2[tid];
    if (tid < 2) sb2[tid] = bc2[tid];
    __syncthreads();

    int g = tid;
    if (g >= ngraphs) return;
    float inv = 1.0f / fmaxf(g_cnt[g], 1.0f);
    float z[32];
#pragma unroll
    for (int f = 0; f < 32; f++) z[f] = g_sums[g * 32 + f] * inv;
    float o0 = sb2[0], o1 = sb2[1];
#pragma unroll
    for (int j = 0; j < 16; j++) {
        float h = sb1[j];
#pragma unroll
        for (int f = 0; f < 32; f++) h += z[f] * sW1[f * 16 + j];
        h = fmaxf(h, 0.f);
        o0 += h * sW2[j * 2 + 0];
        o1 += h * sW2[j * 2 + 1];
    }
    out[g * 2 + 0] = o0;
    out[g * 2 + 1] = o1;
}

// ---------------- launch ----------------
extern "C" void kernel_launch(void* const* d_in, const int* in_sizes, int n_in,
                              void* d_out, int out_size) {
    const float* x   = (const float*)d_in[0];
    const int*   ei  = (const int*)d_in[1];
    const int*   bat = (const int*)d_in[2];
    const float* W1  = (const float*)d_in[3];
    const float* b1  = (const float*)d_in[4];
    const float* g1  = (const float*)d_in[5];
    const float* be1 = (const float*)d_in[6];
    const float* m1  = (const float*)d_in[7];
    const float* v1  = (const float*)d_in[8];
    const float* W2  = (const float*)d_in[9];
    const float* b2  = (const float*)d_in[10];
    const float* g2  = (const float*)d_in[11];
    const float* be2 = (const float*)d_in[12];
    const float* m2  = (const float*)d_in[13];
    const float* v2  = (const float*)d_in[14];
    const float* Wc1 = (const float*)d_in[15];
    const float* bc1 = (const float*)d_in[16];
    const float* Wc2 = (const float*)d_in[17];
    const float* bc2 = (const float*)d_in[18];

    int n  = in_sizes[0] / 64;   // nodes
    int nE = in_sizes[1] / 2;    // edges
    int ngraphs = out_size / 2;

    void* p_cnti;
    cudaGetSymbolAddress(&p_cnti, g_cnt_i);
    cudaMemsetAsync(p_cnti, 0, (size_t)n * sizeof(int));

    bin_kernel<<<(nE + 255) / 256, 256>>>(ei, nE);
    pad_kernel<<<(n + 255) / 256, 256>>>(n);

    gemm1_kernel<<<(n + 63) / 64, 256>>>(x, W1, n);
    pull1_gemm2_kernel<<<(n + 15) / 16, 256>>>(b1, g1, be1, m1, v1, W2, n);
    {
        int warps = (n + 3) / 4;
        pull2_pool_kernel<<<(warps * 32 + 255) / 256, 256>>>(bat, b2, g2, be2, m2, v2, n);
    }
    classifier_kernel<<<1, 512>>>(Wc1, bc1, Wc2, bc2, (float*)d_out, ngraphs);
}

// round 9
// speedup vs baseline: 1.1716x; 1.0261x over previous
#include <cuda_runtime.h>
#include <cuda_fp16.h>

#define EPSV 1e-5f

// ---------------- scratch (device globals; no allocation allowed) ----------------
#define MAXN 100000
#define MAXG 500
#define MAXDEG 64   // Poisson(10): P(deg>64) ~ 1e-30

__device__ int    g_cnt_i[MAXN];              // in-degree / bin cursor
__device__ int    g_csc[MAXN * MAXDEG];       // fixed-stride CSC: src lists per dst
__device__ __half g_hs1h[(MAXN + 1) * 64];    // (x@W1)*dis, fp16 ; row MAXN = zeros
__device__ __half g_hs2h[(MAXN + 1) * 32];    // (y1@W2)*dis, fp16 ; row MAXN = zeros
__device__ float  g_sums[MAXG * 32];
__device__ float  g_cnt[MAXG];

// ---------------- binning: CSC build + zero pool accumulators (fused) ----------------
__global__ void bin_kernel(const int* __restrict__ ei, int nE) {
    int t = blockIdx.x * blockDim.x + threadIdx.x;
    if (t < MAXG * 32) g_sums[t] = 0.f;
    if (t < MAXG) g_cnt[t] = 0.f;
    if (t >= nE) return;
    int s = ei[t];
    int d = ei[nE + t];
    int p = atomicAdd(&g_cnt_i[d], 1);
    if (p < MAXDEG) g_csc[(size_t)d * MAXDEG + p] = s;
}

// ---------------- pad: dummy-fill CSC rows to ceil4 of 4-node-group max ----------------
__global__ void pad_kernel(int n) {
    int t = blockIdx.x * blockDim.x + threadIdx.x;
    if (t < 64) g_hs1h[(size_t)MAXN * 64 + t] = __float2half(0.f);
    if (t < 32) g_hs2h[(size_t)MAXN * 32 + t] = __float2half(0.f);
    if (t >= n) return;

    int q0 = t & ~3;
    int maxd = 0;
#pragma unroll
    for (int k = 0; k < 4; k++) {
        int u = q0 + k;
        int du = (u < n) ? min(g_cnt_i[u], MAXDEG) : 0;
        maxd = max(maxd, du);
    }
    int dpad = min((maxd + 3) & ~3, MAXDEG);
    int d = min(g_cnt_i[t], MAXDEG);
    int* row = &g_csc[(size_t)t * MAXDEG];
    for (int p = d; p < dpad; p++) row[p] = MAXN;
}

// ---------------- layer-1 GEMM: hs1[row] = (x[row] @ W1) * rsqrt(deg+1), fp16 out ----
__global__ void __launch_bounds__(256) gemm1_kernel(const float* __restrict__ X,
                                                    const float* __restrict__ W, int n) {
    __shared__ float sW[64 * 64];
    int tid = threadIdx.x;
    for (int i = tid * 4; i < 64 * 64; i += 256 * 4)
        *reinterpret_cast<float4*>(&sW[i]) = *reinterpret_cast<const float4*>(&W[i]);
    __syncthreads();

    int warp = tid >> 5, lane = tid & 31;
    int row0 = blockIdx.x * 64 + warp * 8;
    if (row0 >= n) return;

    float acc0[8], acc1[8];
#pragma unroll
    for (int r = 0; r < 8; r++) { acc0[r] = 0.f; acc1[r] = 0.f; }

#pragma unroll
    for (int kc = 0; kc < 64; kc += 4) {
        float2 w[4];
#pragma unroll
        for (int kk = 0; kk < 4; kk++)
            w[kk] = *reinterpret_cast<const float2*>(&sW[(kc + kk) * 64 + lane * 2]);
#pragma unroll
        for (int r = 0; r < 8; r++) {
            int row = min(row0 + r, n - 1);
            float4 xv = *reinterpret_cast<const float4*>(&X[(size_t)row * 64 + kc]);
            acc0[r] += xv.x * w[0].x + xv.y * w[1].x + xv.z * w[2].x + xv.w * w[3].x;
            acc1[r] += xv.x * w[0].y + xv.y * w[1].y + xv.z * w[2].y + xv.w * w[3].y;
        }
    }

#pragma unroll
    for (int r = 0; r < 8; r++) {
        int row = row0 + r;
        if (row >= n) break;
        float dv = rsqrtf((float)g_cnt_i[row] + 1.0f);
        __half2 h = __floats2half2_rn(acc0[r] * dv, acc1[r] * dv);
        *reinterpret_cast<__half2*>(&g_hs1h[(size_t)row * 64 + lane * 2]) = h;
    }
}

// fp16 gather helper: load 4 halves (8B) as 4 floats
__device__ __forceinline__ float4 ld_h4(const __half* p) {
    uint2 u = *reinterpret_cast<const uint2*>(p);
    float2 a = __half22float2(*reinterpret_cast<const __half2*>(&u.x));
    float2 b = __half22float2(*reinterpret_cast<const __half2*>(&u.y));
    return make_float4(a.x, a.y, b.x, b.y);
}

// ---------------- fused pull-1 + GEMM-2 ----------------
// Phase 1: 2 nodes/warp, half-warp per node, lane owns 4 cols. Uniform int4 index
// loads; messages accumulated directly in half2 (HADD2), fp32 only in epilogue.
// Phase 2: 4 warps x 4 nodes GEMV (W2 LDS traffic halved vs 8x2).
__global__ void __launch_bounds__(256) pull1_gemm2_kernel(
    const float* __restrict__ b1, const float* __restrict__ g1,
    const float* __restrict__ be1, const float* __restrict__ m1,
    const float* __restrict__ v1, const float* __restrict__ W2, int n) {
    __shared__ float sW2[64 * 32];   // 8 KB
    __shared__ float sy1[16][64];    // 4 KB

    int tid = threadIdx.x;
    for (int i = tid * 4; i < 64 * 32; i += 256 * 4)
        *reinterpret_cast<float4*>(&sW2[i]) = *reinterpret_cast<const float4*>(&W2[i]);
    __syncthreads();

    int wp = tid >> 5;
    int lane = tid & 31;
    int wid = blockIdx.x * 8 + wp;

    // ---- phase 1 (all warps participate; clamped, no early exit) ----
    int half = lane >> 4;
    int li = lane & 15;
    int v = min(wid * 2 + half, n - 1);
    int dt = g_cnt_i[v];
    int d = min(dt, MAXDEG);
    int dmax = max(d, __shfl_xor_sync(0xffffffffu, d, 16));
    int d4 = (dmax + 3) & ~3;
    const int* row = &g_csc[(size_t)v * MAXDEG];
    const __half* hp = &g_hs1h[li * 4];

    __half2 z = __floats2half2_rn(0.f, 0.f);
    __half2 a0 = z, a1 = z, c0 = z, c1 = z;

    for (int i = 0; i < d4; i += 4) {
        int4 s = *reinterpret_cast<const int4*>(row + i);   // uniform in half-warp
        uint2 u0 = *reinterpret_cast<const uint2*>(&hp[(size_t)s.x * 64]);
        uint2 u1 = *reinterpret_cast<const uint2*>(&hp[(size_t)s.y * 64]);
        uint2 u2 = *reinterpret_cast<const uint2*>(&hp[(size_t)s.z * 64]);
        uint2 u3 = *reinterpret_cast<const uint2*>(&hp[(size_t)s.w * 64]);
        a0 = __hadd2(a0, *reinterpret_cast<const __half2*>(&u0.x));
        a1 = __hadd2(a1, *reinterpret_cast<const __half2*>(&u0.y));
        c0 = __hadd2(c0, *reinterpret_cast<const __half2*>(&u1.x));
        c1 = __hadd2(c1, *reinterpret_cast<const __half2*>(&u1.y));
        a0 = __hadd2(a0, *reinterpret_cast<const __half2*>(&u2.x));
        a1 = __hadd2(a1, *reinterpret_cast<const __half2*>(&u2.y));
        c0 = __hadd2(c0, *reinterpret_cast<const __half2*>(&u3.x));
        c1 = __hadd2(c1, *reinterpret_cast<const __half2*>(&u3.y));
    }

    float2 fa0 = __half22float2(a0), fa1 = __half22float2(a1);
    float2 fc0 = __half22float2(c0), fc1 = __half22float2(c1);
    float dvp = rsqrtf((float)dt + 1.0f);
    float4 hv = ld_h4(&g_hs1h[(size_t)v * 64 + li * 4]);
    float pre[4] = {dvp * (fa0.x + fc0.x + hv.x), dvp * (fa0.y + fc0.y + hv.y),
                    dvp * (fa1.x + fc1.x + hv.z), dvp * (fa1.y + fc1.y + hv.w)};
    float4 o;
    float* op = &o.x;
#pragma unroll
    for (int c = 0; c < 4; c++) {
        int f = li * 4 + c;
        float s = g1[f] * rsqrtf(v1[f] + EPSV);
        float sh = (b1[f] - m1[f]) * s + be1[f];
        op[c] = fmaxf(pre[c] * s + sh, 0.f);
    }
    int slot = wp * 2 + half;
    *reinterpret_cast<float4*>(&sy1[slot][li * 4]) = o;
    __syncthreads();

    // ---- phase 2: warps 0-3 only, 4 nodes each; lane = output col ----
    if (wp >= 4) return;
    int base = blockIdx.x * 16 + wp * 4;
    if (base >= n) return;

    float acc[4] = {0.f, 0.f, 0.f, 0.f};
    const float* y0 = sy1[wp * 4 + 0];
    const float* y1p = sy1[wp * 4 + 1];
    const float* y2 = sy1[wp * 4 + 2];
    const float* y3 = sy1[wp * 4 + 3];

#pragma unroll
    for (int kc = 0; kc < 64; kc += 4) {
        float w0 = sW2[(kc + 0) * 32 + lane];
        float w1 = sW2[(kc + 1) * 32 + lane];
        float w2 = sW2[(kc + 2) * 32 + lane];
        float w3 = sW2[(kc + 3) * 32 + lane];
        float4 x0 = *reinterpret_cast<const float4*>(&y0[kc]);
        float4 x1 = *reinterpret_cast<const float4*>(&y1p[kc]);
        float4 x2 = *reinterpret_cast<const float4*>(&y2[kc]);
        float4 x3 = *reinterpret_cast<const float4*>(&y3[kc]);
        acc[0] += x0.x * w0 + x0.y * w1 + x0.z * w2 + x0.w * w3;
        acc[1] += x1.x * w0 + x1.y * w1 + x1.z * w2 + x1.w * w3;
        acc[2] += x2.x * w0 + x2.y * w1 + x2.z * w2 + x2.w * w3;
        acc[3] += x3.x * w0 + x3.y * w1 + x3.z * w2 + x3.w * w3;
    }

#pragma unroll
    for (int j = 0; j < 4; j++) {
        int vo = base + j;
        if (vo < n) {
            float dv = rsqrtf((float)g_cnt_i[vo] + 1.0f);
            g_hs2h[(size_t)vo * 32 + lane] = __float2half_rn(acc[j] * dv);
        }
    }
}

// ---------------- fused pull-2 + mean-pool (half2 accumulate) ----------------
__global__ void __launch_bounds__(256) pull2_pool_kernel(
    const int* __restrict__ batch,
    const float* __restrict__ b2, const float* __restrict__ g2,
    const float* __restrict__ be2, const float* __restrict__ m2,
    const float* __restrict__ v2, int n) {
    int wid = (blockIdx.x * blockDim.x + threadIdx.x) >> 5;
    if (wid * 4 >= n) return;
    int lane = threadIdx.x & 31;
    int q = lane >> 3;
    int li = lane & 7;

    int vraw = wid * 4 + q;
    int v = min(vraw, n - 1);
    int dt = g_cnt_i[v];
    int d = min(dt, MAXDEG);
    int dp = max(d, __shfl_xor_sync(0xffffffffu, d, 8));
    int dmax = max(dp, __shfl_xor_sync(0xffffffffu, dp, 16));
    int d4 = (dmax + 3) & ~3;
    const int* row = &g_csc[(size_t)v * MAXDEG];
    const __half* hp = &g_hs2h[li * 4];

    __half2 z = __floats2half2_rn(0.f, 0.f);
    __half2 a0 = z, a1 = z, c0 = z, c1 = z;

    for (int i = 0; i < d4; i += 4) {
        int4 s = *reinterpret_cast<const int4*>(row + i);   // uniform in quarter-warp
        uint2 u0 = *reinterpret_cast<const uint2*>(&hp[(size_t)s.x * 32]);
        uint2 u1 = *reinterpret_cast<const uint2*>(&hp[(size_t)s.y * 32]);
        uint2 u2 = *reinterpret_cast<const uint2*>(&hp[(size_t)s.z * 32]);
        uint2 u3 = *reinterpret_cast<const uint2*>(&hp[(size_t)s.w * 32]);
        a0 = __hadd2(a0, *reinterpret_cast<const __half2*>(&u0.x));
        a1 = __hadd2(a1, *reinterpret_cast<const __half2*>(&u0.y));
        c0 = __hadd2(c0, *reinterpret_cast<const __half2*>(&u1.x));
        c1 = __hadd2(c1, *reinterpret_cast<const __half2*>(&u1.y));
        a0 = __hadd2(a0, *reinterpret_cast<const __half2*>(&u2.x));
        a1 = __hadd2(a1, *reinterpret_cast<const __half2*>(&u2.y));
        c0 = __hadd2(c0, *reinterpret_cast<const __half2*>(&u3.x));
        c1 = __hadd2(c1, *reinterpret_cast<const __half2*>(&u3.y));
    }

    if (vraw >= n) return;

    float2 fa0 = __half22float2(a0), fa1 = __half22float2(a1);
    float2 fc0 = __half22float2(c0), fc1 = __half22float2(c1);
    float dv = rsqrtf((float)dt + 1.0f);
    float4 hv = ld_h4(&g_hs2h[(size_t)v * 32 + li * 4]);
    float pre[4] = {dv * (fa0.x + fc0.x + hv.x), dv * (fa0.y + fc0.y + hv.y),
                    dv * (fa1.x + fc1.x + hv.z), dv * (fa1.y + fc1.y + hv.w)};
    float o[4];
#pragma unroll
    for (int c = 0; c < 4; c++) {
        int f = li * 4 + c;
        float s = g2[f] * rsqrtf(v2[f] + EPSV);
        float sh = (b2[f] - m2[f]) * s + be2[f];
        o[c] = fmaxf(pre[c] * s + sh, 0.f);
    }

    int g = batch[v];
    float* a = &g_sums[g * 32 + li * 4];
    asm volatile("red.global.add.v4.f32 [%0], {%1,%2,%3,%4};"
                 :: "l"(a), "f"(o[0]), "f"(o[1]), "f"(o[2]), "f"(o[3])
                 : "memory");
    if (li == 0) atomicAdd(&g_cnt[g], 1.0f);
}

// ---------------- classifier ----------------
__global__ void classifier_kernel(const float* __restrict__ Wc1, const float* __restrict__ bc1,
                                  const float* __restrict__ Wc2, const float* __restrict__ bc2,
                                  float* __restrict__ out, int ngraphs) {
    __shared__ float sW1[32 * 16], sb1[16], sW2[16 * 2], sb2[2];
    int tid = threadIdx.x;
    if (tid < 512) sW1[tid] = Wc1[tid];
    if (tid < 16) sb1[tid] = bc1[tid];
    if (tid < 32) sW2[tid] = Wc2[tid];
    if (tid < 2) sb2[tid] = bc2[tid];
    __syncthreads();

    int g = tid;
    if (g >= ngraphs) return;
    float inv = 1.0f / fmaxf(g_cnt[g], 1.0f);
    float z[32];
#pragma unroll
    for (int f = 0; f < 32; f++) z[f] = g_sums[g * 32 + f] * inv;
    float o0 = sb2[0], o1 = sb2[1];
#pragma unroll
    for (int j = 0; j < 16; j++) {
        float h = sb1[j];
#pragma unroll
        for (int f = 0; f < 32; f++) h += z[f] * sW1[f * 16 + j];
        h = fmaxf(h, 0.f);
        o0 += h * sW2[j * 2 + 0];
        o1 += h * sW2[j * 2 + 1];
    }
    out[g * 2 + 0] = o0;
    out[g * 2 + 1] = o1;
}

// ---------------- launch ----------------
extern "C" void kernel_launch(void* const* d_in, const int* in_sizes, int n_in,
                              void* d_out, int out_size) {
    const float* x   = (const float*)d_in[0];
    const int*   ei  = (const int*)d_in[1];
    const int*   bat = (const int*)d_in[2];
    const float* W1  = (const float*)d_in[3];
    const float* b1  = (const float*)d_in[4];
    const float* g1  = (const float*)d_in[5];
    const float* be1 = (const float*)d_in[6];
    const float* m1  = (const float*)d_in[7];
    const float* v1  = (const float*)d_in[8];
    const float* W2  = (const float*)d_in[9];
    const float* b2  = (const float*)d_in[10];
    const float* g2  = (const float*)d_in[11];
    const float* be2 = (const float*)d_in[12];
    const float* m2  = (const float*)d_in[13];
    const float* v2  = (const float*)d_in[14];
    const float* Wc1 = (const float*)d_in[15];
    const float* bc1 = (const float*)d_in[16];
    const float* Wc2 = (const float*)d_in[17];
    const float* bc2 = (const float*)d_in[18];

    int n  = in_sizes[0] / 64;   // nodes
    int nE = in_sizes[1] / 2;    // edges
    int ngraphs = out_size / 2;

    void* p_cnti;
    cudaGetSymbolAddress(&p_cnti, g_cnt_i);
    cudaMemsetAsync(p_cnti, 0, (size_t)n * sizeof(int));

    bin_kernel<<<(nE + 255) / 256, 256>>>(ei, nE);
    pad_kernel<<<(n + 255) / 256, 256>>>(n);

    gemm1_kernel<<<(n + 63) / 64, 256>>>(x, W1, n);
    pull1_gemm2_kernel<<<(n + 15) / 16, 256>>>(b1, g1, be1, m1, v1, W2, n);
    {
        int warps = (n + 3) / 4;
        pull2_pool_kernel<<<(warps * 32 + 255) / 256, 256>>>(bat, b2, g2, be2, m2, v2, n);
    }
    classifier_kernel<<<1, 512>>>(Wc1, bc1, Wc2, bc2, (float*)d_out, ngraphs);
}

// round 10
// speedup vs baseline: 1.2812x; 1.0935x over previous
#include <cuda_runtime.h>
#include <cuda_fp16.h>

#define EPSV 1e-5f

// ---------------- scratch (device globals; no allocation allowed) ----------------
#define MAXN 100000
#define MAXG 500
#define MAXDEG 64   // Poisson(10): P(deg>64) ~ 1e-30

__device__ int      g_cnt_i[MAXN];              // in-degree / bin cursor
__device__ int      g_csc[MAXN * MAXDEG];       // fixed-stride CSC: src lists per dst
__device__ __half   g_hs1h[(MAXN + 1) * 64];    // (x@W1)*dis, fp16 ; row MAXN = zeros
__device__ __half   g_hs2h[(MAXN + 1) * 32];    // (y1@W2)*dis, fp16 ; row MAXN = zeros
__device__ unsigned g_W2p[32 * 32];             // W2 packed: half2(W2[2p][n], W2[2p+1][n])
__device__ float    g_sums[MAXG * 32];
__device__ float    g_cnt[MAXG];

// ---------------- binning: CSC build + zero pool accumulators (fused) ----------------
__global__ void bin_kernel(const int* __restrict__ ei, int nE) {
    int t = blockIdx.x * blockDim.x + threadIdx.x;
    if (t < MAXG * 32) g_sums[t] = 0.f;
    if (t < MAXG) g_cnt[t] = 0.f;
    if (t >= nE) return;
    int s = ei[t];
    int d = ei[nE + t];
    int p = atomicAdd(&g_cnt_i[d], 1);
    if (p < MAXDEG) g_csc[(size_t)d * MAXDEG + p] = s;
}

// ---------------- pad: dummy-fill CSC rows + pack W2 into k-pair half2 -------------
__global__ void pad_kernel(const float* __restrict__ W2, int n) {
    int t = blockIdx.x * blockDim.x + threadIdx.x;
    if (t < 64) g_hs1h[(size_t)MAXN * 64 + t] = __float2half(0.f);
    if (t < 32) g_hs2h[(size_t)MAXN * 32 + t] = __float2half(0.f);
    if (t < 1024) {  // pack W2[64][32] -> g_W2p[(k/2)*32 + n] = half2(W2[k][n], W2[k+1][n])
        int p = t >> 5, c = t & 31;
        __half2 h = __floats2half2_rn(W2[(2 * p) * 32 + c], W2[(2 * p + 1) * 32 + c]);
        g_W2p[t] = *reinterpret_cast<unsigned*>(&h);
    }
    if (t >= n) return;

    int q0 = t & ~3;
    int maxd = 0;
#pragma unroll
    for (int k = 0; k < 4; k++) {
        int u = q0 + k;
        int du = (u < n) ? min(g_cnt_i[u], MAXDEG) : 0;
        maxd = max(maxd, du);
    }
    int dpad = min((maxd + 3) & ~3, MAXDEG);
    int d = min(g_cnt_i[t], MAXDEG);
    int* row = &g_csc[(size_t)t * MAXDEG];
    for (int p = d; p < dpad; p++) row[p] = MAXN;
}

// ---------------- layer-1 GEMM: hs1[row] = (x[row] @ W1) * rsqrt(deg+1), fp16 out ----
__global__ void __launch_bounds__(256) gemm1_kernel(const float* __restrict__ X,
                                                    const float* __restrict__ W, int n) {
    __shared__ float sW[64 * 64];
    int tid = threadIdx.x;
    for (int i = tid * 4; i < 64 * 64; i += 256 * 4)
        *reinterpret_cast<float4*>(&sW[i]) = *reinterpret_cast<const float4*>(&W[i]);
    __syncthreads();

    int warp = tid >> 5, lane = tid & 31;
    int row0 = blockIdx.x * 64 + warp * 8;
    if (row0 >= n) return;

    float acc0[8], acc1[8];
#pragma unroll
    for (int r = 0; r < 8; r++) { acc0[r] = 0.f; acc1[r] = 0.f; }

#pragma unroll
    for (int kc = 0; kc < 64; kc += 4) {
        float2 w[4];
#pragma unroll
        for (int kk = 0; kk < 4; kk++)
            w[kk] = *reinterpret_cast<const float2*>(&sW[(kc + kk) * 64 + lane * 2]);
#pragma unroll
        for (int r = 0; r < 8; r++) {
            int row = min(row0 + r, n - 1);
            float4 xv = *reinterpret_cast<const float4*>(&X[(size_t)row * 64 + kc]);
            acc0[r] += xv.x * w[0].x + xv.y * w[1].x + xv.z * w[2].x + xv.w * w[3].x;
            acc1[r] += xv.x * w[0].y + xv.y * w[1].y + xv.z * w[2].y + xv.w * w[3].y;
        }
    }

#pragma unroll
    for (int r = 0; r < 8; r++) {
        int row = row0 + r;
        if (row >= n) break;
        float dv = rsqrtf((float)g_cnt_i[row] + 1.0f);
        __half2 h = __floats2half2_rn(acc0[r] * dv, acc1[r] * dv);
        *reinterpret_cast<__half2*>(&g_hs1h[(size_t)row * 64 + lane * 2]) = h;
    }
}

// fp16 gather helper: load 4 halves (8B) as 4 floats
__device__ __forceinline__ float4 ld_h4(const __half* p) {
    uint2 u = *reinterpret_cast<const uint2*>(p);
    float2 a = __half22float2(*reinterpret_cast<const __half2*>(&u.x));
    float2 b = __half22float2(*reinterpret_cast<const __half2*>(&u.y));
    return make_float4(a.x, a.y, b.x, b.y);
}

// ---------------- fused pull-1 + tensor-core GEMM-2 ----------------
// Phase 1: 2 nodes/warp, half-warp per node, lane owns 4 cols; half2 accumulate;
//          y1 staged to smem as fp16 with 72-half row stride (conflict-free frags).
// Phase 2: warp 0 computes hs2[16 nodes] = y1 @ W2 via 16x mma.m16n8k16 (fp32 acc).
__global__ void __launch_bounds__(256) pull1_gemm2_kernel(
    const float* __restrict__ b1, const float* __restrict__ g1,
    const float* __restrict__ be1, const float* __restrict__ m1,
    const float* __restrict__ v1, int n) {
    __shared__ __half sy1h[16][72];   // 2.25 KB; row stride 144B

    int tid = threadIdx.x;
    int wp = tid >> 5;
    int lane = tid & 31;
    int wid = blockIdx.x * 8 + wp;

    // ---- phase 1 (all warps; clamped, no early exit) ----
    int half = lane >> 4;
    int li = lane & 15;
    int v = min(wid * 2 + half, n - 1);
    int dt = g_cnt_i[v];
    int d = min(dt, MAXDEG);
    int dmax = max(d, __shfl_xor_sync(0xffffffffu, d, 16));
    int d4 = (dmax + 3) & ~3;
    const int* row = &g_csc[(size_t)v * MAXDEG];
    const __half* hp = &g_hs1h[li * 4];

    __half2 z = __floats2half2_rn(0.f, 0.f);
    __half2 a0 = z, a1 = z, c0 = z, c1 = z;

    for (int i = 0; i < d4; i += 4) {
        int4 s = *reinterpret_cast<const int4*>(row + i);   // uniform in half-warp
        uint2 u0 = *reinterpret_cast<const uint2*>(&hp[(size_t)s.x * 64]);
        uint2 u1 = *reinterpret_cast<const uint2*>(&hp[(size_t)s.y * 64]);
        uint2 u2 = *reinterpret_cast<const uint2*>(&hp[(size_t)s.z * 64]);
        uint2 u3 = *reinterpret_cast<const uint2*>(&hp[(size_t)s.w * 64]);
        a0 = __hadd2(a0, *reinterpret_cast<const __half2*>(&u0.x));
        a1 = __hadd2(a1, *reinterpret_cast<const __half2*>(&u0.y));
        c0 = __hadd2(c0, *reinterpret_cast<const __half2*>(&u1.x));
        c1 = __hadd2(c1, *reinterpret_cast<const __half2*>(&u1.y));
        a0 = __hadd2(a0, *reinterpret_cast<const __half2*>(&u2.x));
        a1 = __hadd2(a1, *reinterpret_cast<const __half2*>(&u2.y));
        c0 = __hadd2(c0, *reinterpret_cast<const __half2*>(&u3.x));
        c1 = __hadd2(c1, *reinterpret_cast<const __half2*>(&u3.y));
    }

    float2 fa0 = __half22float2(a0), fa1 = __half22float2(a1);
    float2 fc0 = __half22float2(c0), fc1 = __half22float2(c1);
    float dvp = rsqrtf((float)dt + 1.0f);
    float4 hv = ld_h4(&g_hs1h[(size_t)v * 64 + li * 4]);
    float pre[4] = {dvp * (fa0.x + fc0.x + hv.x), dvp * (fa0.y + fc0.y + hv.y),
                    dvp * (fa1.x + fc1.x + hv.z), dvp * (fa1.y + fc1.y + hv.w)};
    float o[4];
#pragma unroll
    for (int c = 0; c < 4; c++) {
        int f = li * 4 + c;
        float s = g1[f] * rsqrtf(v1[f] + EPSV);
        float sh = (b1[f] - m1[f]) * s + be1[f];
        o[c] = fmaxf(pre[c] * s + sh, 0.f);
    }
    int slot = wp * 2 + half;
    __half2 p0 = __floats2half2_rn(o[0], o[1]);
    __half2 p1 = __floats2half2_rn(o[2], o[3]);
    uint2 pk;
    pk.x = *reinterpret_cast<unsigned*>(&p0);
    pk.y = *reinterpret_cast<unsigned*>(&p1);
    *reinterpret_cast<uint2*>(&sy1h[slot][li * 4]) = pk;
    __syncthreads();

    // ---- phase 2: warp 0 only — 16 nodes x 32 cols = 16 HMMA m16n8k16 ----
    if (wp != 0) return;
    int base = blockIdx.x * 16;

    int g = lane >> 2;       // group 0..7
    int tg = lane & 3;       // thread-in-group 0..3

    // B fragments (block-invariant): b[ks][ns][2]
    unsigned bfr[4][4][2];
#pragma unroll
    for (int ks = 0; ks < 4; ks++)
#pragma unroll
        for (int ns = 0; ns < 4; ns++) {
            bfr[ks][ns][0] = g_W2p[(ks * 8 + tg) * 32 + ns * 8 + g];
            bfr[ks][ns][1] = g_W2p[(ks * 8 + tg + 4) * 32 + ns * 8 + g];
        }

    float dfr[4][4];
#pragma unroll
    for (int ns = 0; ns < 4; ns++)
#pragma unroll
        for (int j = 0; j < 4; j++) dfr[ns][j] = 0.f;

#pragma unroll
    for (int ks = 0; ks < 4; ks++) {
        unsigned afr[4];
        afr[0] = *reinterpret_cast<const unsigned*>(&sy1h[g][ks * 16 + 2 * tg]);
        afr[1] = *reinterpret_cast<const unsigned*>(&sy1h[g + 8][ks * 16 + 2 * tg]);
        afr[2] = *reinterpret_cast<const unsigned*>(&sy1h[g][ks * 16 + 2 * tg + 8]);
        afr[3] = *reinterpret_cast<const unsigned*>(&sy1h[g + 8][ks * 16 + 2 * tg + 8]);
#pragma unroll
        for (int ns = 0; ns < 4; ns++) {
            asm volatile(
                "mma.sync.aligned.m16n8k16.row.col.f32.f16.f16.f32 "
                "{%0,%1,%2,%3}, {%4,%5,%6,%7}, {%8,%9}, {%0,%1,%2,%3};"
                : "+f"(dfr[ns][0]), "+f"(dfr[ns][1]), "+f"(dfr[ns][2]), "+f"(dfr[ns][3])
                : "r"(afr[0]), "r"(afr[1]), "r"(afr[2]), "r"(afr[3]),
                  "r"(bfr[ks][ns][0]), "r"(bfr[ks][ns][1]));
        }
    }

    // epilogue: D row g -> node base+g, row g+8 -> node base+g+8; cols ns*8+2tg(+1)
    int nodeLo = base + g;
    int nodeHi = base + g + 8;
    float dvLo = (nodeLo < n) ? rsqrtf((float)g_cnt_i[nodeLo] + 1.0f) : 0.f;
    float dvHi = (nodeHi < n) ? rsqrtf((float)g_cnt_i[nodeHi] + 1.0f) : 0.f;
#pragma unroll
    for (int ns = 0; ns < 4; ns++) {
        int c0i = ns * 8 + 2 * tg;
        if (nodeLo < n) {
            __half2 hlo = __floats2half2_rn(dfr[ns][0] * dvLo, dfr[ns][1] * dvLo);
            *reinterpret_cast<__half2*>(&g_hs2h[(size_t)nodeLo * 32 + c0i]) = hlo;
        }
        if (nodeHi < n) {
            __half2 hhi = __floats2half2_rn(dfr[ns][2] * dvHi, dfr[ns][3] * dvHi);
            *reinterpret_cast<__half2*>(&g_hs2h[(size_t)nodeHi * 32 + c0i]) = hhi;
        }
    }
}

// ---------------- fused pull-2 + mean-pool (half2 accumulate) ----------------
__global__ void __launch_bounds__(256) pull2_pool_kernel(
    const int* __restrict__ batch,
    const float* __restrict__ b2, const float* __restrict__ g2,
    const float* __restrict__ be2, const float* __restrict__ m2,
    const float* __restrict__ v2, int n) {
    int wid = (blockIdx.x * blockDim.x + threadIdx.x) >> 5;
    if (wid * 4 >= n) return;
    int lane = threadIdx.x & 31;
    int q = lane >> 3;
    int li = lane & 7;

    int vraw = wid * 4 + q;
    int v = min(vraw, n - 1);
    int dt = g_cnt_i[v];
    int d = min(dt, MAXDEG);
    int dp = max(d, __shfl_xor_sync(0xffffffffu, d, 8));
    int dmax = max(dp, __shfl_xor_sync(0xffffffffu, dp, 16));
    int d4 = (dmax + 3) & ~3;
    const int* row = &g_csc[(size_t)v * MAXDEG];
    const __half* hp = &g_hs2h[li * 4];

    __half2 z = __floats2half2_rn(0.f, 0.f);
    __half2 a0 = z, a1 = z, c0 = z, c1 = z;

    for (int i = 0; i < d4; i += 4) {
        int4 s = *reinterpret_cast<const int4*>(row + i);   // uniform in quarter-warp
        uint2 u0 = *reinterpret_cast<const uint2*>(&hp[(size_t)s.x * 32]);
        uint2 u1 = *reinterpret_cast<const uint2*>(&hp[(size_t)s.y * 32]);
        uint2 u2 = *reinterpret_cast<const uint2*>(&hp[(size_t)s.z * 32]);
        uint2 u3 = *reinterpret_cast<const uint2*>(&hp[(size_t)s.w * 32]);
        a0 = __hadd2(a0, *reinterpret_cast<const __half2*>(&u0.x));
        a1 = __hadd2(a1, *reinterpret_cast<const __half2*>(&u0.y));
        c0 = __hadd2(c0, *reinterpret_cast<const __half2*>(&u1.x));
        c1 = __hadd2(c1, *reinterpret_cast<const __half2*>(&u1.y));
        a0 = __hadd2(a0, *reinterpret_cast<const __half2*>(&u2.x));
        a1 = __hadd2(a1, *reinterpret_cast<const __half2*>(&u2.y));
        c0 = __hadd2(c0, *reinterpret_cast<const __half2*>(&u3.x));
        c1 = __hadd2(c1, *reinterpret_cast<const __half2*>(&u3.y));
    }

    if (vraw >= n) return;

    float2 fa0 = __half22float2(a0), fa1 = __half22float2(a1);
    float2 fc0 = __half22float2(c0), fc1 = __half22float2(c1);
    float dv = rsqrtf((float)dt + 1.0f);
    float4 hv = ld_h4(&g_hs2h[(size_t)v * 32 + li * 4]);
    float pre[4] = {dv * (fa0.x + fc0.x + hv.x), dv * (fa0.y + fc0.y + hv.y),
                    dv * (fa1.x + fc1.x + hv.z), dv * (fa1.y + fc1.y + hv.w)};
    float o[4];
#pragma unroll
    for (int c = 0; c < 4; c++) {
        int f = li * 4 + c;
        float s = g2[f] * rsqrtf(v2[f] + EPSV);
        float sh = (b2[f] - m2[f]) * s + be2[f];
        o[c] = fmaxf(pre[c] * s + sh, 0.f);
    }

    int g = batch[v];
    float* a = &g_sums[g * 32 + li * 4];
    asm volatile("red.global.add.v4.f32 [%0], {%1,%2,%3,%4};"
                 :: "l"(a), "f"(o[0]), "f"(o[1]), "f"(o[2]), "f"(o[3])
                 : "memory");
    if (li == 0) atomicAdd(&g_cnt[g], 1.0f);
}

// ---------------- classifier ----------------
__global__ void classifier_kernel(const float* __restrict__ Wc1, const float* __restrict__ bc1,
                                  const float* __restrict__ Wc2, const float* __restrict__ bc2,
                                  float* __restrict__ out, int ngraphs) {
    __shared__ float sW1[32 * 16], sb1[16], sW2[16 * 2], sb2[2];
    int tid = threadIdx.x;
    if (tid < 512) sW1[tid] = Wc1[tid];
    if (tid < 16) sb1[tid] = bc1[tid];
    if (tid < 32) sW2[tid] = Wc2[tid];
    if (tid < 2) sb2[tid] = bc2[tid];
    __syncthreads();

    int g = tid;
    if (g >= ngraphs) return;
    float inv = 1.0f / fmaxf(g_cnt[g], 1.0f);
    float z[32];
#pragma unroll
    for (int f = 0; f < 32; f++) z[f] = g_sums[g * 32 + f] * inv;
    float o0 = sb2[0], o1 = sb2[1];
#pragma unroll
    for (int j = 0; j < 16; j++) {
        float h = sb1[j];
#pragma unroll
        for (int f = 0; f < 32; f++) h += z[f] * sW1[f * 16 + j];
        h = fmaxf(h, 0.f);
        o0 += h * sW2[j * 2 + 0];
        o1 += h * sW2[j * 2 + 1];
    }
    out[g * 2 + 0] = o0;
    out[g * 2 + 1] = o1;
}

// ---------------- launch ----------------
extern "C" void kernel_launch(void* const* d_in, const int* in_sizes, int n_in,
                              void* d_out, int out_size) {
    const float* x   = (const float*)d_in[0];
    const int*   ei  = (const int*)d_in[1];
    const int*   bat = (const int*)d_in[2];
    const float* W1  = (const float*)d_in[3];
    const float* b1  = (const float*)d_in[4];
    const float* g1  = (const float*)d_in[5];
    const float* be1 = (const float*)d_in[6];
    const float* m1  = (const float*)d_in[7];
    const float* v1  = (const float*)d_in[8];
    const float* W2  = (const float*)d_in[9];
    const float* b2  = (const float*)d_in[10];
    const float* g2  = (const float*)d_in[11];
    const float* be2 = (const float*)d_in[12];
    const float* m2  = (const float*)d_in[13];
    const float* v2  = (const float*)d_in[14];
    const float* Wc1 = (const float*)d_in[15];
    const float* bc1 = (const float*)d_in[16];
    const float* Wc2 = (const float*)d_in[17];
    const float* bc2 = (const float*)d_in[18];

    int n  = in_sizes[0] / 64;   // nodes
    int nE = in_sizes[1] / 2;    // edges
    int ngraphs = out_size / 2;

    void* p_cnti;
    cudaGetSymbolAddress(&p_cnti, g_cnt_i);
    cudaMemsetAsync(p_cnti, 0, (size_t)n * sizeof(int));

    bin_kernel<<<(nE + 255) / 256, 256>>>(ei, nE);
    pad_kernel<<<(n + 255) / 256, 256>>>(W2, n);

    gemm1_kernel<<<(n + 63) / 64, 256>>>(x, W1, n);
    pull1_gemm2_kernel<<<(n + 15) / 16, 256>>>(b1, g1, be1, m1, v1, n);
    {
        int warps = (n + 3) / 4;
        pull2_pool_kernel<<<(warps * 32 + 255) / 256, 256>>>(bat, b2, g2, be2, m2, v2, n);
    }
    classifier_kernel<<<1, 512>>>(Wc1, bc1, Wc2, bc2, (float*)d_out, ngraphs);
}

// round 11
// speedup vs baseline: 1.6007x; 1.2494x over previous
#include <cuda_runtime.h>
#include <cuda_fp16.h>

#define EPSV 1e-5f

// ---------------- scratch (device globals; no allocation allowed) ----------------
#define MAXN 100000
#define MAXG 500
#define MAXDEG 64   // Poisson(10): P(deg>64) ~ 1e-30

__device__ int      g_cnt_i[MAXN];              // in-degree / bin cursor
__device__ int      g_csc[MAXN * MAXDEG];       // fixed-stride CSC: src lists per dst
__device__ __half   g_hs1h[(MAXN + 1) * 64];    // (x@W1)*dis, fp16 ; row MAXN = zeros
__device__ __half   g_hs2h[(MAXN + 1) * 32];    // (y1@W2)*dis, fp16 ; row MAXN = zeros
__device__ unsigned g_W1p[32 * 64];             // W1 packed: half2(W1[2p][c], W1[2p+1][c])
__device__ unsigned g_W2p[32 * 32];             // W2 packed: half2(W2[2p][c], W2[2p+1][c])
__device__ float    g_sums[MAXG * 32];
__device__ float    g_cnt[MAXG];

// ---------------- binning: CSC build + zero pool accumulators (fused) ----------------
__global__ void bin_kernel(const int* __restrict__ ei, int nE) {
    int t = blockIdx.x * blockDim.x + threadIdx.x;
    if (t < MAXG * 32) g_sums[t] = 0.f;
    if (t < MAXG) g_cnt[t] = 0.f;
    if (t >= nE) return;
    int s = ei[t];
    int d = ei[nE + t];
    int p = atomicAdd(&g_cnt_i[d], 1);
    if (p < MAXDEG) g_csc[(size_t)d * MAXDEG + p] = s;
}

// ---------------- pad: dummy-fill CSC rows + pack W1/W2 into k-pair half2 ----------
__global__ void pad_kernel(const float* __restrict__ W1, const float* __restrict__ W2, int n) {
    int t = blockIdx.x * blockDim.x + threadIdx.x;
    if (t < 64) g_hs1h[(size_t)MAXN * 64 + t] = __float2half(0.f);
    if (t < 32) g_hs2h[(size_t)MAXN * 32 + t] = __float2half(0.f);
    if (t < 2048) {  // W1[64][64] -> g_W1p[(k/2)*64 + c]
        int p = t >> 6, c = t & 63;
        __half2 h = __floats2half2_rn(W1[(2 * p) * 64 + c], W1[(2 * p + 1) * 64 + c]);
        g_W1p[t] = *reinterpret_cast<unsigned*>(&h);
    }
    if (t < 1024) {  // W2[64][32] -> g_W2p[(k/2)*32 + c]
        int p = t >> 5, c = t & 31;
        __half2 h = __floats2half2_rn(W2[(2 * p) * 32 + c], W2[(2 * p + 1) * 32 + c]);
        g_W2p[t] = *reinterpret_cast<unsigned*>(&h);
    }
    if (t >= n) return;

    int q0 = t & ~3;
    int maxd = 0;
#pragma unroll
    for (int k = 0; k < 4; k++) {
        int u = q0 + k;
        int du = (u < n) ? min(g_cnt_i[u], MAXDEG) : 0;
        maxd = max(maxd, du);
    }
    int dpad = min((maxd + 3) & ~3, MAXDEG);
    int d = min(g_cnt_i[t], MAXDEG);
    int* row = &g_csc[(size_t)t * MAXDEG];
    for (int p = d; p < dpad; p++) row[p] = MAXN;
}

// ---------------- layer-1 GEMM via tensor cores ----------------
// hs1[row] = half(x[row] @ W1) * rsqrt(deg+1). 8 warps x 16 rows = 128 rows/block.
// Fragment mappings identical to the validated pull1 phase-2 HMMA.
__global__ void __launch_bounds__(256) gemm1_kernel(const float* __restrict__ X, int n) {
    int wp = threadIdx.x >> 5, lane = threadIdx.x & 31;
    int g = lane >> 2, tg = lane & 3;
    int r0 = blockIdx.x * 128 + wp * 16;
    if (r0 >= n) return;
    int rA = min(r0 + g, n - 1);
    int rB = min(r0 + g + 8, n - 1);
    const float* xA = &X[(size_t)rA * 64];
    const float* xB = &X[(size_t)rB * 64];

    float dfr[8][4];
#pragma unroll
    for (int ns = 0; ns < 8; ns++)
#pragma unroll
        for (int j = 0; j < 4; j++) dfr[ns][j] = 0.f;

#pragma unroll
    for (int ks = 0; ks < 4; ks++) {
        float2 fA0 = *reinterpret_cast<const float2*>(&xA[ks * 16 + 2 * tg]);
        float2 fB0 = *reinterpret_cast<const float2*>(&xB[ks * 16 + 2 * tg]);
        float2 fA1 = *reinterpret_cast<const float2*>(&xA[ks * 16 + 2 * tg + 8]);
        float2 fB1 = *reinterpret_cast<const float2*>(&xB[ks * 16 + 2 * tg + 8]);
        __half2 hA0 = __floats2half2_rn(fA0.x, fA0.y);
        __half2 hB0 = __floats2half2_rn(fB0.x, fB0.y);
        __half2 hA1 = __floats2half2_rn(fA1.x, fA1.y);
        __half2 hB1 = __floats2half2_rn(fB1.x, fB1.y);
        unsigned a0 = *reinterpret_cast<unsigned*>(&hA0);
        unsigned a1 = *reinterpret_cast<unsigned*>(&hB0);
        unsigned a2 = *reinterpret_cast<unsigned*>(&hA1);
        unsigned a3 = *reinterpret_cast<unsigned*>(&hB1);
#pragma unroll
        for (int ns = 0; ns < 8; ns++) {
            unsigned b0 = g_W1p[(ks * 8 + tg) * 64 + ns * 8 + g];
            unsigned b1 = g_W1p[(ks * 8 + tg + 4) * 64 + ns * 8 + g];
            asm volatile(
                "mma.sync.aligned.m16n8k16.row.col.f32.f16.f16.f32 "
                "{%0,%1,%2,%3}, {%4,%5,%6,%7}, {%8,%9}, {%0,%1,%2,%3};"
                : "+f"(dfr[ns][0]), "+f"(dfr[ns][1]), "+f"(dfr[ns][2]), "+f"(dfr[ns][3])
                : "r"(a0), "r"(a1), "r"(a2), "r"(a3), "r"(b0), "r"(b1));
        }
    }

    float dvA = rsqrtf((float)g_cnt_i[rA] + 1.0f);
    float dvB = rsqrtf((float)g_cnt_i[rB] + 1.0f);
    bool okA = (r0 + g) < n, okB = (r0 + g + 8) < n;
#pragma unroll
    for (int ns = 0; ns < 8; ns++) {
        int c = ns * 8 + 2 * tg;
        if (okA) {
            __half2 h = __floats2half2_rn(dfr[ns][0] * dvA, dfr[ns][1] * dvA);
            *reinterpret_cast<__half2*>(&g_hs1h[(size_t)rA * 64 + c]) = h;
        }
        if (okB) {
            __half2 h = __floats2half2_rn(dfr[ns][2] * dvB, dfr[ns][3] * dvB);
            *reinterpret_cast<__half2*>(&g_hs1h[(size_t)rB * 64 + c]) = h;
        }
    }
}

// fp16 gather helper: load 4 halves (8B) as 4 floats
__device__ __forceinline__ float4 ld_h4(const __half* p) {
    uint2 u = *reinterpret_cast<const uint2*>(p);
    float2 a = __half22float2(*reinterpret_cast<const __half2*>(&u.x));
    float2 b = __half22float2(*reinterpret_cast<const __half2*>(&u.y));
    return make_float4(a.x, a.y, b.x, b.y);
}

// ---------------- fused pull-1 + tensor-core GEMM-2 ----------------
// Phase 1: 2 nodes/warp, half-warp per node; pipelined int4 index prefetch.
// Phase 2: warps 0-3 each compute one 8-col slice of hs2[16 nodes] via HMMA.
__global__ void __launch_bounds__(256) pull1_gemm2_kernel(
    const float* __restrict__ b1, const float* __restrict__ g1,
    const float* __restrict__ be1, const float* __restrict__ m1,
    const float* __restrict__ v1, int n) {
    __shared__ __half sy1h[16][72];   // 2.25 KB; 144B row stride (conflict-free frags)

    int tid = threadIdx.x;
    int wp = tid >> 5;
    int lane = tid & 31;
    int wid = blockIdx.x * 8 + wp;

    // ---- phase 1 (all warps; clamped, no early exit) ----
    int half = lane >> 4;
    int li = lane & 15;
    int v = min(wid * 2 + half, n - 1);
    int dt = g_cnt_i[v];
    int d = min(dt, MAXDEG);
    int dmax = max(d, __shfl_xor_sync(0xffffffffu, d, 16));
    int d4 = (dmax + 3) & ~3;
    const int* row = &g_csc[(size_t)v * MAXDEG];
    const __half* hp = &g_hs1h[li * 4];

    __half2 z = __floats2half2_rn(0.f, 0.f);
    __half2 a0 = z, a1 = z, c0 = z, c1 = z;

    int4 s = *reinterpret_cast<const int4*>(row);   // prefetch (safe: in-bounds; unused if d4==0)
    for (int i = 0; i < d4; i += 4) {
        int4 sn = (i + 4 < d4) ? *reinterpret_cast<const int4*>(row + i + 4) : s;
        uint2 u0 = *reinterpret_cast<const uint2*>(&hp[(size_t)s.x * 64]);
        uint2 u1 = *reinterpret_cast<const uint2*>(&hp[(size_t)s.y * 64]);
        uint2 u2 = *reinterpret_cast<const uint2*>(&hp[(size_t)s.z * 64]);
        uint2 u3 = *reinterpret_cast<const uint2*>(&hp[(size_t)s.w * 64]);
        a0 = __hadd2(a0, *reinterpret_cast<const __half2*>(&u0.x));
        a1 = __hadd2(a1, *reinterpret_cast<const __half2*>(&u0.y));
        c0 = __hadd2(c0, *reinterpret_cast<const __half2*>(&u1.x));
        c1 = __hadd2(c1, *reinterpret_cast<const __half2*>(&u1.y));
        a0 = __hadd2(a0, *reinterpret_cast<const __half2*>(&u2.x));
        a1 = __hadd2(a1, *reinterpret_cast<const __half2*>(&u2.y));
        c0 = __hadd2(c0, *reinterpret_cast<const __half2*>(&u3.x));
        c1 = __hadd2(c1, *reinterpret_cast<const __half2*>(&u3.y));
        s = sn;
    }

    float2 fa0 = __half22float2(a0), fa1 = __half22float2(a1);
    float2 fc0 = __half22float2(c0), fc1 = __half22float2(c1);
    float dvp = rsqrtf((float)dt + 1.0f);
    float4 hv = ld_h4(&g_hs1h[(size_t)v * 64 + li * 4]);
    float pre[4] = {dvp * (fa0.x + fc0.x + hv.x), dvp * (fa0.y + fc0.y + hv.y),
                    dvp * (fa1.x + fc1.x + hv.z), dvp * (fa1.y + fc1.y + hv.w)};
    float o[4];
#pragma unroll
    for (int c = 0; c < 4; c++) {
        int f = li * 4 + c;
        float sc = g1[f] * rsqrtf(v1[f] + EPSV);
        float sh = (b1[f] - m1[f]) * sc + be1[f];
        o[c] = fmaxf(pre[c] * sc + sh, 0.f);
    }
    int slot = wp * 2 + half;
    __half2 p0 = __floats2half2_rn(o[0], o[1]);
    __half2 p1 = __floats2half2_rn(o[2], o[3]);
    uint2 pk;
    pk.x = *reinterpret_cast<unsigned*>(&p0);
    pk.y = *reinterpret_cast<unsigned*>(&p1);
    *reinterpret_cast<uint2*>(&sy1h[slot][li * 4]) = pk;
    __syncthreads();

    // ---- phase 2: warps 0-3, warp wp handles n-slice ns = wp (8 cols) ----
    if (wp >= 4) return;
    int base = blockIdx.x * 16;
    int g = lane >> 2;       // group 0..7
    int tg = lane & 3;       // thread-in-group 0..3
    int ns = wp;

    float dfr[4] = {0.f, 0.f, 0.f, 0.f};
#pragma unroll
    for (int ks = 0; ks < 4; ks++) {
        unsigned afr0 = *reinterpret_cast<const unsigned*>(&sy1h[g][ks * 16 + 2 * tg]);
        unsigned afr1 = *reinterpret_cast<const unsigned*>(&sy1h[g + 8][ks * 16 + 2 * tg]);
        unsigned afr2 = *reinterpret_cast<const unsigned*>(&sy1h[g][ks * 16 + 2 * tg + 8]);
        unsigned afr3 = *reinterpret_cast<const unsigned*>(&sy1h[g + 8][ks * 16 + 2 * tg + 8]);
        unsigned b0 = g_W2p[(ks * 8 + tg) * 32 + ns * 8 + g];
        unsigned b1 = g_W2p[(ks * 8 + tg + 4) * 32 + ns * 8 + g];
        asm volatile(
            "mma.sync.aligned.m16n8k16.row.col.f32.f16.f16.f32 "
            "{%0,%1,%2,%3}, {%4,%5,%6,%7}, {%8,%9}, {%0,%1,%2,%3};"
            : "+f"(dfr[0]), "+f"(dfr[1]), "+f"(dfr[2]), "+f"(dfr[3])
            : "r"(afr0), "r"(afr1), "r"(afr2), "r"(afr3), "r"(b0), "r"(b1));
    }

    int nodeLo = base + g;
    int nodeHi = base + g + 8;
    int c0i = ns * 8 + 2 * tg;
    if (nodeLo < n) {
        float dvLo = rsqrtf((float)g_cnt_i[nodeLo] + 1.0f);
        __half2 h = __floats2half2_rn(dfr[0] * dvLo, dfr[1] * dvLo);
        *reinterpret_cast<__half2*>(&g_hs2h[(size_t)nodeLo * 32 + c0i]) = h;
    }
    if (nodeHi < n) {
        float dvHi = rsqrtf((float)g_cnt_i[nodeHi] + 1.0f);
        __half2 h = __floats2half2_rn(dfr[2] * dvHi, dfr[3] * dvHi);
        *reinterpret_cast<__half2*>(&g_hs2h[(size_t)nodeHi * 32 + c0i]) = h;
    }
}

// ---------------- fused pull-2 + mean-pool (half2 accumulate, pipelined idx) -------
__global__ void __launch_bounds__(256) pull2_pool_kernel(
    const int* __restrict__ batch,
    const float* __restrict__ b2, const float* __restrict__ g2,
    const float* __restrict__ be2, const float* __restrict__ m2,
    const float* __restrict__ v2, int n) {
    int wid = (blockIdx.x * blockDim.x + threadIdx.x) >> 5;
    if (wid * 4 >= n) return;
    int lane = threadIdx.x & 31;
    int q = lane >> 3;
    int li = lane & 7;

    int vraw = wid * 4 + q;
    int v = min(vraw, n - 1);
    int dt = g_cnt_i[v];
    int d = min(dt, MAXDEG);
    int dp = max(d, __shfl_xor_sync(0xffffffffu, d, 8));
    int dmax = max(dp, __shfl_xor_sync(0xffffffffu, dp, 16));
    int d4 = (dmax + 3) & ~3;
    const int* row = &g_csc[(size_t)v * MAXDEG];
    const __half* hp = &g_hs2h[li * 4];

    __half2 z = __floats2half2_rn(0.f, 0.f);
    __half2 a0 = z, a1 = z, c0 = z, c1 = z;

    int4 s = *reinterpret_cast<const int4*>(row);
    for (int i = 0; i < d4; i += 4) {
        int4 sn = (i + 4 < d4) ? *reinterpret_cast<const int4*>(row + i + 4) : s;
        uint2 u0 = *reinterpret_cast<const uint2*>(&hp[(size_t)s.x * 32]);
        uint2 u1 = *reinterpret_cast<const uint2*>(&hp[(size_t)s.y * 32]);
        uint2 u2 = *reinterpret_cast<const uint2*>(&hp[(size_t)s.z * 32]);
        uint2 u3 = *reinterpret_cast<const uint2*>(&hp[(size_t)s.w * 32]);
        a0 = __hadd2(a0, *reinterpret_cast<const __half2*>(&u0.x));
        a1 = __hadd2(a1, *reinterpret_cast<const __half2*>(&u0.y));
        c0 = __hadd2(c0, *reinterpret_cast<const __half2*>(&u1.x));
        c1 = __hadd2(c1, *reinterpret_cast<const __half2*>(&u1.y));
        a0 = __hadd2(a0, *reinterpret_cast<const __half2*>(&u2.x));
        a1 = __hadd2(a1, *reinterpret_cast<const __half2*>(&u2.y));
        c0 = __hadd2(c0, *reinterpret_cast<const __half2*>(&u3.x));
        c1 = __hadd2(c1, *reinterpret_cast<const __half2*>(&u3.y));
        s = sn;
    }

    if (vraw >= n) return;

    float2 fa0 = __half22float2(a0), fa1 = __half22float2(a1);
    float2 fc0 = __half22float2(c0), fc1 = __half22float2(c1);
    float dv = rsqrtf((float)dt + 1.0f);
    float4 hv = ld_h4(&g_hs2h[(size_t)v * 32 + li * 4]);
    float pre[4] = {dv * (fa0.x + fc0.x + hv.x), dv * (fa0.y + fc0.y + hv.y),
                    dv * (fa1.x + fc1.x + hv.z), dv * (fa1.y + fc1.y + hv.w)};
    float o[4];
#pragma unroll
    for (int c = 0; c < 4; c++) {
        int f = li * 4 + c;
        float sc = g2[f] * rsqrtf(v2[f] + EPSV);
        float sh = (b2[f] - m2[f]) * sc + be2[f];
        o[c] = fmaxf(pre[c] * sc + sh, 0.f);
    }

    int g = batch[v];
    float* a = &g_sums[g * 32 + li * 4];
    asm volatile("red.global.add.v4.f32 [%0], {%1,%2,%3,%4};"
                 :: "l"(a), "f"(o[0]), "f"(o[1]), "f"(o[2]), "f"(o[3])
                 : "memory");
    if (li == 0) atomicAdd(&g_cnt[g], 1.0f);
}

// ---------------- classifier ----------------
__global__ void classifier_kernel(const float* __restrict__ Wc1, const float* __restrict__ bc1,
                                  const float* __restrict__ Wc2, const float* __restrict__ bc2,
                                  float* __restrict__ out, int ngraphs) {
    __shared__ float sW1[32 * 16], sb1[16], sW2[16 * 2], sb2[2];
    int tid = threadIdx.x;
    if (tid < 512) sW1[tid] = Wc1[tid];
    if (tid < 16) sb1[tid] = bc1[tid];
    if (tid < 32) sW2[tid] = Wc2[tid];
    if (tid < 2) sb2[tid] = bc2[tid];
    __syncthreads();

    int g = tid;
    if (g >= ngraphs) return;
    float inv = 1.0f / fmaxf(g_cnt[g], 1.0f);
    float z[32];
#pragma unroll
    for (int f = 0; f < 32; f++) z[f] = g_sums[g * 32 + f] * inv;
    float o0 = sb2[0], o1 = sb2[1];
#pragma unroll
    for (int j = 0; j < 16; j++) {
        float h = sb1[j];
#pragma unroll
        for (int f = 0; f < 32; f++) h += z[f] * sW1[f * 16 + j];
        h = fmaxf(h, 0.f);
        o0 += h * sW2[j * 2 + 0];
        o1 += h * sW2[j * 2 + 1];
    }
    out[g * 2 + 0] = o0;
    out[g * 2 + 1] = o1;
}

// ---------------- launch ----------------
extern "C" void kernel_launch(void* const* d_in, const int* in_sizes, int n_in,
                              void* d_out, int out_size) {
    const float* x   = (const float*)d_in[0];
    const int*   ei  = (const int*)d_in[1];
    const int*   bat = (const int*)d_in[2];
    const float* W1  = (const float*)d_in[3];
    const float* b1  = (const float*)d_in[4];
    const float* g1  = (const float*)d_in[5];
    const float* be1 = (const float*)d_in[6];
    const float* m1  = (const float*)d_in[7];
    const float* v1  = (const float*)d_in[8];
    const float* W2  = (const float*)d_in[9];
    const float* b2  = (const float*)d_in[10];
    const float* g2  = (const float*)d_in[11];
    const float* be2 = (const float*)d_in[12];
    const float* m2  = (const float*)d_in[13];
    const float* v2  = (const float*)d_in[14];
    const float* Wc1 = (const float*)d_in[15];
    const float* bc1 = (const float*)d_in[16];
    const float* Wc2 = (const float*)d_in[17];
    const float* bc2 = (const float*)d_in[18];

    int n  = in_sizes[0] / 64;   // nodes
    int nE = in_sizes[1] / 2;    // edges
    int ngraphs = out_size / 2;

    void* p_cnti;
    cudaGetSymbolAddress(&p_cnti, g_cnt_i);
    cudaMemsetAsync(p_cnti, 0, (size_t)n * sizeof(int));

    bin_kernel<<<(nE + 255) / 256, 256>>>(ei, nE);
    pad_kernel<<<(n + 255) / 256, 256>>>(W1, W2, n);

    gemm1_kernel<<<(n + 127) / 128, 256>>>(x, n);
    pull1_gemm2_kernel<<<(n + 15) / 16, 256>>>(b1, g1, be1, m1, v1, n);
    {
        int warps = (n + 3) / 4;
        pull2_pool_kernel<<<(warps * 32 + 255) / 256, 256>>>(bat, b2, g2, be2, m2, v2, n);
    }
    classifier_kernel<<<1, 512>>>(Wc1, bc1, Wc2, bc2, (float*)d_out, ngraphs);
}

// round 12
// speedup vs baseline: 1.6143x; 1.0085x over previous
#include <cuda_runtime.h>
#include <cuda_fp16.h>

#define EPSV 1e-5f

// ---------------- scratch (device globals; no allocation allowed) ----------------
#define MAXN 100000
#define MAXG 500
#define MAXDEG 64   // Poisson(10): P(deg>64) ~ 1e-30

__device__ int      g_cnt_i[MAXN];              // in-degree / bin cursor
__device__ int      g_csc[MAXN * MAXDEG];       // fixed-stride CSC: src lists per dst
__device__ float    g_dis[MAXN];                // rsqrt(deg+1)
__device__ __half   g_hs1h[(MAXN + 1) * 64];    // (x@W1)*dis, fp16 ; row MAXN = zeros
__device__ __half   g_hs2h[(MAXN + 1) * 32];    // (y1@W2)*dis, fp16 ; row MAXN = zeros
__device__ unsigned g_W1p[32 * 64];             // W1 packed k-pair half2
__device__ unsigned g_W2p[32 * 32];             // W2 packed k-pair half2
__device__ float    g_sc1[64], g_sh1[64];       // BN1 folded scale/shift
__device__ float    g_sc2[32], g_sh2[32];       // BN2 folded scale/shift
__device__ float    g_sums[MAXG * 32];
__device__ float    g_cnt[MAXG];

// ---------------- binning: CSC build + zero pool accumulators (fused) ----------------
__global__ void bin_kernel(const int* __restrict__ ei, int nE) {
    int t = blockIdx.x * blockDim.x + threadIdx.x;
    if (t < MAXG * 32) g_sums[t] = 0.f;
    if (t < MAXG) g_cnt[t] = 0.f;
    if (t >= nE) return;
    int s = ei[t];
    int d = ei[nE + t];
    int p = atomicAdd(&g_cnt_i[d], 1);
    if (p < MAXDEG) g_csc[(size_t)d * MAXDEG + p] = s;
}

// ---------------- pad: CSC dummy-fill + W packing + dis + BN constant folding ------
__global__ void pad_kernel(const float* __restrict__ W1, const float* __restrict__ W2,
                           const float* __restrict__ b1, const float* __restrict__ g1,
                           const float* __restrict__ be1, const float* __restrict__ m1,
                           const float* __restrict__ v1,
                           const float* __restrict__ b2, const float* __restrict__ g2,
                           const float* __restrict__ be2, const float* __restrict__ m2,
                           const float* __restrict__ v2, int n) {
    int t = blockIdx.x * blockDim.x + threadIdx.x;
    if (t < 64) g_hs1h[(size_t)MAXN * 64 + t] = __float2half(0.f);
    if (t < 32) g_hs2h[(size_t)MAXN * 32 + t] = __float2half(0.f);
    if (t < 2048) {  // W1[64][64] -> g_W1p[(k/2)*64 + c]
        int p = t >> 6, c = t & 63;
        __half2 h = __floats2half2_rn(W1[(2 * p) * 64 + c], W1[(2 * p + 1) * 64 + c]);
        g_W1p[t] = *reinterpret_cast<unsigned*>(&h);
    }
    if (t < 1024) {  // W2[64][32] -> g_W2p[(k/2)*32 + c]
        int p = t >> 5, c = t & 31;
        __half2 h = __floats2half2_rn(W2[(2 * p) * 32 + c], W2[(2 * p + 1) * 32 + c]);
        g_W2p[t] = *reinterpret_cast<unsigned*>(&h);
    }
    if (t < 64) {
        float s = g1[t] * rsqrtf(v1[t] + EPSV);
        g_sc1[t] = s;
        g_sh1[t] = (b1[t] - m1[t]) * s + be1[t];
    }
    if (t < 32) {
        float s = g2[t] * rsqrtf(v2[t] + EPSV);
        g_sc2[t] = s;
        g_sh2[t] = (b2[t] - m2[t]) * s + be2[t];
    }
    if (t >= n) return;

    g_dis[t] = rsqrtf((float)g_cnt_i[t] + 1.0f);

    int q0 = t & ~3;
    int maxd = 0;
#pragma unroll
    for (int k = 0; k < 4; k++) {
        int u = q0 + k;
        int du = (u < n) ? min(g_cnt_i[u], MAXDEG) : 0;
        maxd = max(maxd, du);
    }
    int dpad = min((maxd + 3) & ~3, MAXDEG);
    int d = min(g_cnt_i[t], MAXDEG);
    int* row = &g_csc[(size_t)t * MAXDEG];
    for (int p = d; p < dpad; p++) row[p] = MAXN;
}

// ---------------- layer-1 GEMM via tensor cores ----------------
__global__ void __launch_bounds__(256) gemm1_kernel(const float* __restrict__ X, int n) {
    int wp = threadIdx.x >> 5, lane = threadIdx.x & 31;
    int g = lane >> 2, tg = lane & 3;
    int r0 = blockIdx.x * 128 + wp * 16;
    if (r0 >= n) return;
    int rA = min(r0 + g, n - 1);
    int rB = min(r0 + g + 8, n - 1);
    const float* xA = &X[(size_t)rA * 64];
    const float* xB = &X[(size_t)rB * 64];

    float dfr[8][4];
#pragma unroll
    for (int ns = 0; ns < 8; ns++)
#pragma unroll
        for (int j = 0; j < 4; j++) dfr[ns][j] = 0.f;

#pragma unroll
    for (int ks = 0; ks < 4; ks++) {
        float2 fA0 = *reinterpret_cast<const float2*>(&xA[ks * 16 + 2 * tg]);
        float2 fB0 = *reinterpret_cast<const float2*>(&xB[ks * 16 + 2 * tg]);
        float2 fA1 = *reinterpret_cast<const float2*>(&xA[ks * 16 + 2 * tg + 8]);
        float2 fB1 = *reinterpret_cast<const float2*>(&xB[ks * 16 + 2 * tg + 8]);
        __half2 hA0 = __floats2half2_rn(fA0.x, fA0.y);
        __half2 hB0 = __floats2half2_rn(fB0.x, fB0.y);
        __half2 hA1 = __floats2half2_rn(fA1.x, fA1.y);
        __half2 hB1 = __floats2half2_rn(fB1.x, fB1.y);
        unsigned a0 = *reinterpret_cast<unsigned*>(&hA0);
        unsigned a1 = *reinterpret_cast<unsigned*>(&hB0);
        unsigned a2 = *reinterpret_cast<unsigned*>(&hA1);
        unsigned a3 = *reinterpret_cast<unsigned*>(&hB1);
#pragma unroll
        for (int ns = 0; ns < 8; ns++) {
            unsigned b0 = g_W1p[(ks * 8 + tg) * 64 + ns * 8 + g];
            unsigned b1 = g_W1p[(ks * 8 + tg + 4) * 64 + ns * 8 + g];
            asm volatile(
                "mma.sync.aligned.m16n8k16.row.col.f32.f16.f16.f32 "
                "{%0,%1,%2,%3}, {%4,%5,%6,%7}, {%8,%9}, {%0,%1,%2,%3};"
                : "+f"(dfr[ns][0]), "+f"(dfr[ns][1]), "+f"(dfr[ns][2]), "+f"(dfr[ns][3])
                : "r"(a0), "r"(a1), "r"(a2), "r"(a3), "r"(b0), "r"(b1));
        }
    }

    float dvA = g_dis[rA];
    float dvB = g_dis[rB];
    bool okA = (r0 + g) < n, okB = (r0 + g + 8) < n;
#pragma unroll
    for (int ns = 0; ns < 8; ns++) {
        int c = ns * 8 + 2 * tg;
        if (okA) {
            __half2 h = __floats2half2_rn(dfr[ns][0] * dvA, dfr[ns][1] * dvA);
            *reinterpret_cast<__half2*>(&g_hs1h[(size_t)rA * 64 + c]) = h;
        }
        if (okB) {
            __half2 h = __floats2half2_rn(dfr[ns][2] * dvB, dfr[ns][3] * dvB);
            *reinterpret_cast<__half2*>(&g_hs1h[(size_t)rB * 64 + c]) = h;
        }
    }
}

// ---------------- fused pull-1 + tensor-core GEMM-2 ----------------
// Phase 1: 4 nodes/warp, 8 lanes/node, lane owns 8 cols (LDG.128 gathers), half2
//          accumulate, pipelined int4 index prefetch; block covers 32 nodes.
// Phase 2: all 8 warps: warp = (mtile, ns); 32x32x64 GEMM via HMMA m16n8k16.
__global__ void __launch_bounds__(256) pull1_gemm2_kernel(int n) {
    __shared__ __half sy1h[32][72];   // 4.5 KB; 144B row stride (conflict-free frags)

    int tid = threadIdx.x;
    int wp = tid >> 5;
    int lane = tid & 31;
    int q = lane >> 3;               // node within warp (0..3)
    int li = lane & 7;               // lane-in-group: owns cols li*8 .. li*8+7

    int nodeIdx = blockIdx.x * 32 + wp * 4 + q;
    int v = min(nodeIdx, n - 1);
    int d = min(g_cnt_i[v], MAXDEG);
    int dp = max(d, __shfl_xor_sync(0xffffffffu, d, 8));
    int dmax = max(dp, __shfl_xor_sync(0xffffffffu, dp, 16));
    int d4 = (dmax + 3) & ~3;        // pad_kernel wrote dummies exactly to this bound
    const int* row = &g_csc[(size_t)v * MAXDEG];
    const __half* hp = &g_hs1h[li * 8];

    __half2 z = __floats2half2_rn(0.f, 0.f);
    __half2 a[4] = {z, z, z, z};     // edges 0,2 of each quad
    __half2 c[4] = {z, z, z, z};     // edges 1,3

    int4 s = *reinterpret_cast<const int4*>(row);   // prefetch (in-bounds; unused if d4==0)
    for (int i = 0; i < d4; i += 4) {
        int4 sn = (i + 4 < d4) ? *reinterpret_cast<const int4*>(row + i + 4) : s;
        uint4 u0 = *reinterpret_cast<const uint4*>(&hp[(size_t)s.x * 64]);
        uint4 u1 = *reinterpret_cast<const uint4*>(&hp[(size_t)s.y * 64]);
        uint4 u2 = *reinterpret_cast<const uint4*>(&hp[(size_t)s.z * 64]);
        uint4 u3 = *reinterpret_cast<const uint4*>(&hp[(size_t)s.w * 64]);
        a[0] = __hadd2(a[0], *reinterpret_cast<const __half2*>(&u0.x));
        a[1] = __hadd2(a[1], *reinterpret_cast<const __half2*>(&u0.y));
        a[2] = __hadd2(a[2], *reinterpret_cast<const __half2*>(&u0.z));
        a[3] = __hadd2(a[3], *reinterpret_cast<const __half2*>(&u0.w));
        c[0] = __hadd2(c[0], *reinterpret_cast<const __half2*>(&u1.x));
        c[1] = __hadd2(c[1], *reinterpret_cast<const __half2*>(&u1.y));
        c[2] = __hadd2(c[2], *reinterpret_cast<const __half2*>(&u1.z));
        c[3] = __hadd2(c[3], *reinterpret_cast<const __half2*>(&u1.w));
        a[0] = __hadd2(a[0], *reinterpret_cast<const __half2*>(&u2.x));
        a[1] = __hadd2(a[1], *reinterpret_cast<const __half2*>(&u2.y));
        a[2] = __hadd2(a[2], *reinterpret_cast<const __half2*>(&u2.z));
        a[3] = __hadd2(a[3], *reinterpret_cast<const __half2*>(&u2.w));
        c[0] = __hadd2(c[0], *reinterpret_cast<const __half2*>(&u3.x));
        c[1] = __hadd2(c[1], *reinterpret_cast<const __half2*>(&u3.y));
        c[2] = __hadd2(c[2], *reinterpret_cast<const __half2*>(&u3.z));
        c[3] = __hadd2(c[3], *reinterpret_cast<const __half2*>(&u3.w));
        s = sn;
    }

    // epilogue: y1 = relu(BN(dis * (agg + hs1[v])))
    float dvp = g_dis[v];
    uint4 uv = *reinterpret_cast<const uint4*>(&g_hs1h[(size_t)v * 64 + li * 8]);
    const __half2* hvp = reinterpret_cast<const __half2*>(&uv);
    float4 sc0 = *reinterpret_cast<const float4*>(&g_sc1[li * 8]);
    float4 sc1 = *reinterpret_cast<const float4*>(&g_sc1[li * 8 + 4]);
    float4 sh0 = *reinterpret_cast<const float4*>(&g_sh1[li * 8]);
    float4 sh1 = *reinterpret_cast<const float4*>(&g_sh1[li * 8 + 4]);
    const float* scp = &sc0.x;   // sc0,sc1 contiguous? not guaranteed; handle per-vec
    float o[8];
#pragma unroll
    for (int k = 0; k < 4; k++) {
        float2 fa = __half22float2(a[k]);
        float2 fc = __half22float2(c[k]);
        float2 fv = __half22float2(hvp[k]);
        o[2 * k]     = dvp * (fa.x + fc.x + fv.x);
        o[2 * k + 1] = dvp * (fa.y + fc.y + fv.y);
    }
    float scv[8] = {sc0.x, sc0.y, sc0.z, sc0.w, sc1.x, sc1.y, sc1.z, sc1.w};
    float shv[8] = {sh0.x, sh0.y, sh0.z, sh0.w, sh1.x, sh1.y, sh1.z, sh1.w};
    (void)scp;
    __half2 pk[4];
#pragma unroll
    for (int k = 0; k < 4; k++) {
        float y0 = fmaxf(o[2 * k] * scv[2 * k] + shv[2 * k], 0.f);
        float y1 = fmaxf(o[2 * k + 1] * scv[2 * k + 1] + shv[2 * k + 1], 0.f);
        pk[k] = __floats2half2_rn(y0, y1);
    }
    int slot = wp * 4 + q;
    *reinterpret_cast<uint4*>(&sy1h[slot][li * 8]) = *reinterpret_cast<uint4*>(pk);
    __syncthreads();

    // ---- phase 2: 8 warps = 2 mtiles x 4 n-slices; HMMA m16n8k16 over K=64 ----
    int mtile = wp >> 2;
    int ns = wp & 3;
    int base = blockIdx.x * 32 + mtile * 16;
    int g = lane >> 2, tg = lane & 3;
    const __half(*sa)[72] = &sy1h[mtile * 16];

    float dfr[4] = {0.f, 0.f, 0.f, 0.f};
#pragma unroll
    for (int ks = 0; ks < 4; ks++) {
        unsigned afr0 = *reinterpret_cast<const unsigned*>(&sa[g][ks * 16 + 2 * tg]);
        unsigned afr1 = *reinterpret_cast<const unsigned*>(&sa[g + 8][ks * 16 + 2 * tg]);
        unsigned afr2 = *reinterpret_cast<const unsigned*>(&sa[g][ks * 16 + 2 * tg + 8]);
        unsigned afr3 = *reinterpret_cast<const unsigned*>(&sa[g + 8][ks * 16 + 2 * tg + 8]);
        unsigned b0 = g_W2p[(ks * 8 + tg) * 32 + ns * 8 + g];
        unsigned b1 = g_W2p[(ks * 8 + tg + 4) * 32 + ns * 8 + g];
        asm volatile(
            "mma.sync.aligned.m16n8k16.row.col.f32.f16.f16.f32 "
            "{%0,%1,%2,%3}, {%4,%5,%6,%7}, {%8,%9}, {%0,%1,%2,%3};"
            : "+f"(dfr[0]), "+f"(dfr[1]), "+f"(dfr[2]), "+f"(dfr[3])
            : "r"(afr0), "r"(afr1), "r"(afr2), "r"(afr3), "r"(b0), "r"(b1));
    }

    int nodeLo = base + g;
    int nodeHi = base + g + 8;
    int c0i = ns * 8 + 2 * tg;
    if (nodeLo < n) {
        float dvLo = g_dis[nodeLo];
        __half2 h = __floats2half2_rn(dfr[0] * dvLo, dfr[1] * dvLo);
        *reinterpret_cast<__half2*>(&g_hs2h[(size_t)nodeLo * 32 + c0i]) = h;
    }
    if (nodeHi < n) {
        float dvHi = g_dis[nodeHi];
        __half2 h = __floats2half2_rn(dfr[2] * dvHi, dfr[3] * dvHi);
        *reinterpret_cast<__half2*>(&g_hs2h[(size_t)nodeHi * 32 + c0i]) = h;
    }
}

// fp16 gather helper: load 4 halves (8B) as 4 floats
__device__ __forceinline__ float4 ld_h4(const __half* p) {
    uint2 u = *reinterpret_cast<const uint2*>(p);
    float2 a = __half22float2(*reinterpret_cast<const __half2*>(&u.x));
    float2 b = __half22float2(*reinterpret_cast<const __half2*>(&u.y));
    return make_float4(a.x, a.y, b.x, b.y);
}

// ---------------- fused pull-2 + mean-pool (half2 accumulate, folded consts) -------
__global__ void __launch_bounds__(256) pull2_pool_kernel(const int* __restrict__ batch, int n) {
    int wid = (blockIdx.x * blockDim.x + threadIdx.x) >> 5;
    if (wid * 4 >= n) return;
    int lane = threadIdx.x & 31;
    int q = lane >> 3;
    int li = lane & 7;

    int vraw = wid * 4 + q;
    int v = min(vraw, n - 1);
    int d = min(g_cnt_i[v], MAXDEG);
    int dp = max(d, __shfl_xor_sync(0xffffffffu, d, 8));
    int dmax = max(dp, __shfl_xor_sync(0xffffffffu, dp, 16));
    int d4 = (dmax + 3) & ~3;
    const int* row = &g_csc[(size_t)v * MAXDEG];
    const __half* hp = &g_hs2h[li * 4];

    __half2 z = __floats2half2_rn(0.f, 0.f);
    __half2 a0 = z, a1 = z, c0 = z, c1 = z;

    int4 s = *reinterpret_cast<const int4*>(row);
    for (int i = 0; i < d4; i += 4) {
        int4 sn = (i + 4 < d4) ? *reinterpret_cast<const int4*>(row + i + 4) : s;
        uint2 u0 = *reinterpret_cast<const uint2*>(&hp[(size_t)s.x * 32]);
        uint2 u1 = *reinterpret_cast<const uint2*>(&hp[(size_t)s.y * 32]);
        uint2 u2 = *reinterpret_cast<const uint2*>(&hp[(size_t)s.z * 32]);
        uint2 u3 = *reinterpret_cast<const uint2*>(&hp[(size_t)s.w * 32]);
        a0 = __hadd2(a0, *reinterpret_cast<const __half2*>(&u0.x));
        a1 = __hadd2(a1, *reinterpret_cast<const __half2*>(&u0.y));
        c0 = __hadd2(c0, *reinterpret_cast<const __half2*>(&u1.x));
        c1 = __hadd2(c1, *reinterpret_cast<const __half2*>(&u1.y));
        a0 = __hadd2(a0, *reinterpret_cast<const __half2*>(&u2.x));
        a1 = __hadd2(a1, *reinterpret_cast<const __half2*>(&u2.y));
        c0 = __hadd2(c0, *reinterpret_cast<const __half2*>(&u3.x));
        c1 = __hadd2(c1, *reinterpret_cast<const __half2*>(&u3.y));
        s = sn;
    }

    if (vraw >= n) return;

    float2 fa0 = __half22float2(a0), fa1 = __half22float2(a1);
    float2 fc0 = __half22float2(c0), fc1 = __half22float2(c1);
    float dv = g_dis[v];
    float4 hv = ld_h4(&g_hs2h[(size_t)v * 32 + li * 4]);
    float4 sc = *reinterpret_cast<const float4*>(&g_sc2[li * 4]);
    float4 sh = *reinterpret_cast<const float4*>(&g_sh2[li * 4]);
    float o[4];
    o[0] = fmaxf(dv * (fa0.x + fc0.x + hv.x) * sc.x + sh.x, 0.f);
    o[1] = fmaxf(dv * (fa0.y + fc0.y + hv.y) * sc.y + sh.y, 0.f);
    o[2] = fmaxf(dv * (fa1.x + fc1.x + hv.z) * sc.z + sh.z, 0.f);
    o[3] = fmaxf(dv * (fa1.y + fc1.y + hv.w) * sc.w + sh.w, 0.f);

    int g = batch[v];
    float* a = &g_sums[g * 32 + li * 4];
    asm volatile("red.global.add.v4.f32 [%0], {%1,%2,%3,%4};"
                 :: "l"(a), "f"(o[0]), "f"(o[1]), "f"(o[2]), "f"(o[3])
                 : "memory");
    if (li == 0) atomicAdd(&g_cnt[g], 1.0f);
}

// ---------------- classifier ----------------
__global__ void classifier_kernel(const float* __restrict__ Wc1, const float* __restrict__ bc1,
                                  const float* __restrict__ Wc2, const float* __restrict__ bc2,
                                  float* __restrict__ out, int ngraphs) {
    __shared__ float sW1[32 * 16], sb1[16], sW2[16 * 2], sb2[2];
    int tid = threadIdx.x;
    if (tid < 512) sW1[tid] = Wc1[tid];
    if (tid < 16) sb1[tid] = bc1[tid];
    if (tid < 32) sW2[tid] = Wc2[tid];
    if (tid < 2) sb2[tid] = bc2[tid];
    __syncthreads();

    int g = tid;
    if (g >= ngraphs) return;
    float inv = 1.0f / fmaxf(g_cnt[g], 1.0f);
    float z[32];
#pragma unroll
    for (int f = 0; f < 32; f++) z[f] = g_sums[g * 32 + f] * inv;
    float o0 = sb2[0], o1 = sb2[1];
#pragma unroll
    for (int j = 0; j < 16; j++) {
        float h = sb1[j];
#pragma unroll
        for (int f = 0; f < 32; f++) h += z[f] * sW1[f * 16 + j];
        h = fmaxf(h, 0.f);
        o0 += h * sW2[j * 2 + 0];
        o1 += h * sW2[j * 2 + 1];
    }
    out[g * 2 + 0] = o0;
    out[g * 2 + 1] = o1;
}

// ---------------- launch ----------------
extern "C" void kernel_launch(void* const* d_in, const int* in_sizes, int n_in,
                              void* d_out, int out_size) {
    const float* x   = (const float*)d_in[0];
    const int*   ei  = (const int*)d_in[1];
    const int*   bat = (const int*)d_in[2];
    const float* W1  = (const float*)d_in[3];
    const float* b1  = (const float*)d_in[4];
    const float* g1  = (const float*)d_in[5];
    const float* be1 = (const float*)d_in[6];
    const float* m1  = (const float*)d_in[7];
    const float* v1  = (const float*)d_in[8];
    const float* W2  = (const float*)d_in[9];
    const float* b2  = (const float*)d_in[10];
    const float* g2  = (const float*)d_in[11];
    const float* be2 = (const float*)d_in[12];
    const float* m2  = (const float*)d_in[13];
    const float* v2  = (const float*)d_in[14];
    const float* Wc1 = (const float*)d_in[15];
    const float* bc1 = (const float*)d_in[16];
    const float* Wc2 = (const float*)d_in[17];
    const float* bc2 = (const float*)d_in[18];

    int n  = in_sizes[0] / 64;   // nodes
    int nE = in_sizes[1] / 2;    // edges
    int ngraphs = out_size / 2;

    void* p_cnti;
    cudaGetSymbolAddress(&p_cnti, g_cnt_i);
    cudaMemsetAsync(p_cnti, 0, (size_t)n * sizeof(int));

    bin_kernel<<<(nE + 255) / 256, 256>>>(ei, nE);
    pad_kernel<<<(n + 255) / 256, 256>>>(W1, W2, b1, g1, be1, m1, v1,
                                         b2, g2, be2, m2, v2, n);

    gemm1_kernel<<<(n + 127) / 128, 256>>>(x, n);
    pull1_gemm2_kernel<<<(n + 31) / 32, 256>>>(n);
    {
        int warps = (n + 3) / 4;
        pull2_pool_kernel<<<(warps * 32 + 255) / 256, 256>>>(bat, n);
    }
    classifier_kernel<<<1, 512>>>(Wc1, bc1, Wc2, bc2, (float*)d_out, ngraphs);
}